// round 6
// baseline (speedup 1.0000x reference)
#include <cuda_runtime.h>
#include <math.h>

#define NMOL 256
#define NPER 32
#define NNODE 8192
#define EPM 992                  // 32*31 edges per molecule
#define ETOT (NMOL*EPM)          // 253952
#define SD 256
#define ED 32
#define MSG_IN 546
#define MSG_OUT 353
#define NTH 1024                 // threads per CTA (32 warps, 2 molecules)
#define HALF 512                 // threads per molecule
#define HROWS 16

typedef unsigned long long u64;

// global scratch (sanctioned __device__ arrays)
__device__ float g_e[(long)ETOT*ED];                    // edge features (32.5MB, L2)
__device__ __align__(16) float g_w2t[5*64*32*4];        // transposed W2e  [l][c4][k][4]
__device__ __align__(16) float g_Q [(long)NMOL*NPER*SD];// per-layer Q rows
__device__ __align__(16) float g_S0[(long)NMOL*NPER*SD];// per-layer S0 rows
__device__ __align__(16) float g_s [(long)NMOL*NPER*SD];// node scalar features

struct MolSM {
    float P   [NPER][SD];   // s @ W1a                         32KB
    float hdn [NPER][SD];   // hidden activations, tgt j       32KB
    float esm2[NPER][2*ED]; // e rows for tgt j, duplicated     8KB
    float s0q [2][SD];      // partial sums                     2KB
    float pos [NPER][3];
    float npos[NPER][3];
    float dbuf[NPER];
    float abuf[NPER];
    float rnb [NPER][3];
    float pdpart[16][3];
};

struct SM {
    MolSM m[2];
    float W1c [ED][SD];     // e-part of W1 (shared)           32KB
    float w2s [64*32*4];    // C2 weights (shared)             32KB
    float w2p [SD];         // pos column of W2 (shared)        1KB
};

__device__ __forceinline__ float silu_f(float v){
    return v * (1.0f / (1.0f + __expf(-v)));
}
__device__ __forceinline__ u64 pack2(float x, float y){
    u64 r; asm("mov.b64 %0, {%1, %2};" : "=l"(r) : "f"(x), "f"(y)); return r;
}
__device__ __forceinline__ void unpack2(u64 v, float& x, float& y){
    asm("mov.b64 {%0, %1}, %2;" : "=f"(x), "=f"(y) : "l"(v));
}
__device__ __forceinline__ u64 fma2(u64 a, u64 b, u64 c){
    u64 d; asm("fma.rn.f32x2 %0, %1, %2, %3;" : "=l"(d) : "l"(a), "l"(b), "l"(c)); return d;
}
__device__ __forceinline__ u64 add2(u64 a, u64 b){
    u64 d; asm("add.rn.f32x2 %0, %1, %2;" : "=l"(d) : "l"(a), "l"(b)); return d;
}
__device__ __forceinline__ u64 dup2(float x){ return pack2(x,x); }

// prep: g_w2t[l*8192 + c4*128 + k*4 + cc] = gW2[(l*256+4*c4+cc)*353 + 321 + k]
__global__ void prep_kernel(const float* __restrict__ gW2){
    int idx = blockIdx.x*256 + threadIdx.x;
    if (idx >= 5*8192) return;
    int l = idx >> 13; int rem = idx & 8191;
    int c4 = rem >> 7; int rem2 = rem & 127;
    int k = rem2 >> 2; int cc = rem2 & 3;
    g_w2t[idx] = gW2[((long)l*256 + 4*c4 + cc)*MSG_OUT + 321 + k];
}

__global__ void __launch_bounds__(NTH,1) dec_kernel(
    const float* __restrict__ x,   const float* __restrict__ z,
    const float* __restrict__ rot, const float* __restrict__ eattr,
    const float* __restrict__ Wam, const float* __restrict__ bam,
    const float* __restrict__ Wbm, const float* __restrict__ bbm,
    const float* __restrict__ gW1, const float* __restrict__ gb1,
    const float* __restrict__ gW2, const float* __restrict__ gb2,
    const float* __restrict__ Wh1, const float* __restrict__ bh1,
    const float* __restrict__ Wh2, const float* __restrict__ bh2,
    const float* __restrict__ We1, const float* __restrict__ be1,
    const float* __restrict__ We2, const float* __restrict__ be2,
    float* __restrict__ outA, float* __restrict__ outB, float* __restrict__ outP)
{
    extern __shared__ float smraw[];
    SM* sm = (SM*)smraw;
    const int tid  = threadIdx.x;
    const int mh   = tid >> 9;        // molecule half (0/1)
    const int t    = tid & 511;       // thread id within half
    const int lane = t & 31;
    const int wrp  = t >> 5;          // 0..15 (half-local)
    const int mol  = blockIdx.x*2 + mh;
    const int nodeBase = mol * NPER;
    const long ebase   = (long)mol * EPM;
    const int c  = t & 255;           // column (0..255)
    const int hh = t >> 8;            // row-half (0/1)
    const int r0 = hh * HROWS;
    const int p  = t & 127;           // col-pair index for [B]
    const int q4 = t >> 7;            // row-quarter (0..3) for [B]
    const int rq = q4 * 8;
    MolSM* ms = &sm->m[mh];
    float* Qg  = g_Q  + (size_t)mol*NPER*SD;
    float* S0g = g_S0 + (size_t)mol*NPER*SD;
    float* sg  = g_s  + (size_t)mol*NPER*SD;

    // ------------------------------------------------------------------
    // Embed: h = [x,z] @ Wam + bam ; s = h[:,:256]; pos = rot @ h[:,256:259]
    // ------------------------------------------------------------------
    {
        float* xz = &ms->hdn[0][0];                 // reuse: 32*80 floats
        for (int idx = t; idx < NPER*80; idx += HALF){
            int i = idx / 80, k = idx % 80;
            xz[idx] = (k < 16) ? x[(nodeBase+i)*16 + k]
                               : z[(nodeBase+i)*64 + (k-16)];
        }
        __syncthreads();
        float acc[HROWS];
#pragma unroll
        for (int r=0;r<HROWS;r++) acc[r]=0.f;
        for (int kg=0; kg<20; kg++){
            float w0=Wam[(4*kg+0)*259+c], w1=Wam[(4*kg+1)*259+c];
            float w2v=Wam[(4*kg+2)*259+c], w3=Wam[(4*kg+3)*259+c];
#pragma unroll
            for (int r=0;r<HROWS;r++){
                float4 v = ((const float4*)xz)[(r0+r)*20+kg];
                acc[r] += v.x*w0 + v.y*w1 + v.z*w2v + v.w*w3;
            }
        }
        float b = bam[c];
#pragma unroll
        for (int r=0;r<HROWS;r++) sg[(r0+r)*SD + c] = acc[r] + b;
        if (t < 96){                                // pos3 into npos (tmp)
            int i = t/3, cc = t%3;
            float a = bam[256+cc];
            for (int k=0;k<80;k++) a += xz[i*80+k]*Wam[k*259+256+cc];
            ms->npos[i][cc] = a;
        }
        __syncthreads();
        if (t < 96){
            int i = t/3, cc = t%3;
            float pv = 0.f;
#pragma unroll
            for (int q=0;q<3;q++) pv += rot[mol*9 + cc*3 + q]*ms->npos[i][q];
            ms->pos[i][cc] = pv;
        }
    }

    // ------------------------------------------------------------------
    // e init: e = edge_attr @ Wbm + bbm   (into global scratch)
    // ------------------------------------------------------------------
    for (int idx = t; idx < EPM*ED; idx += HALF){
        int eL = idx >> 5, k = idx & 31;
        const float* ea = &eattr[(ebase+eL)*5];
        float a = bbm[k];
#pragma unroll
        for (int q=0;q<5;q++) a += ea[q]*Wbm[q*ED+k];
        g_e[(ebase+eL)*ED + k] = a;
    }
    __syncthreads();

    // ------------------------------------------------------------------
    // 5 message-passing layers
    // ------------------------------------------------------------------
    for (int l=0; l<5; l++){
        const float* W1 = gW1 + (long)l*MSG_IN*SD;
        const float* b1 = gb1 + l*SD;
        const float* W2 = gW2 + (long)l*SD*MSG_OUT;
        const float* b2 = gb2 + l*MSG_OUT;

        // stage shared weights with ALL 1024 threads
        for (int idx = tid; idx < ED*SD; idx += NTH)
            sm->W1c[idx>>8][idx&255] = W1[512*SD + idx];
        {
            const float4* src = (const float4*)(g_w2t + l*8192);
            float4* dst = (float4*)sm->w2s;
            for (int idx = tid; idx < 2048; idx += NTH) dst[idx] = src[idx];
        }
        if (tid < 256) sm->w2p[tid] = W2[tid*MSG_OUT + 320];
        if (t < 96) ms->npos[t/3][t%3] = 0.f;

        // P = s@W1a (pass 1) -> SMEM
        {
            float acc[HROWS];
#pragma unroll
            for (int r=0;r<HROWS;r++) acc[r]=0.f;
            for (int kg=0; kg<64; kg++){
                float wa0=W1[(4*kg+0)*SD+c], wa1=W1[(4*kg+1)*SD+c];
                float wa2=W1[(4*kg+2)*SD+c], wa3=W1[(4*kg+3)*SD+c];
#pragma unroll
                for (int r=0;r<HROWS;r++){
                    const float4 v = __ldg((const float4*)&sg[(r0+r)*SD + 4*kg]);
                    acc[r] += v.x*wa0 + v.y*wa1 + v.z*wa2 + v.w*wa3;
                }
            }
#pragma unroll
            for (int r=0;r<HROWS;r++) ms->P[r0+r][c]=acc[r];
        }
        // Q = s@W1b + b1 (pass 2) -> global scratch
        {
            float acc[HROWS];
#pragma unroll
            for (int r=0;r<HROWS;r++) acc[r]=0.f;
            for (int kg=0; kg<64; kg++){
                float wb0=W1[(256+4*kg+0)*SD+c], wb1=W1[(256+4*kg+1)*SD+c];
                float wb2=W1[(256+4*kg+2)*SD+c], wb3=W1[(256+4*kg+3)*SD+c];
#pragma unroll
                for (int r=0;r<HROWS;r++){
                    const float4 v = __ldg((const float4*)&sg[(r0+r)*SD + 4*kg]);
                    acc[r] += v.x*wb0 + v.y*wb1 + v.z*wb2 + v.w*wb3;
                }
            }
            float bb = b1[c];
#pragma unroll
            for (int r=0;r<HROWS;r++) Qg[(r0+r)*SD + c] = acc[r]+bb;
        }
        __syncthreads();

        // per-layer packed constants for [B] (col-pair 2p,2p+1)
        const u64 w1d2 = __ldg((const u64*)&W1[544*SD + 2*p]);
        const u64 w1e2 = __ldg((const u64*)&W1[545*SD + 2*p]);
        const float b2p = __ldg(&b2[320]);
        const float* wt = sm->w2s + lane*4;

        for (int j=0; j<NPER; j++){
            // [A] fold prev pdpart into npos; stage e rows (duplicated) + geometry
            if (j>0 && t<3){
                float sum=0.f;
#pragma unroll
                for (int w=0;w<16;w++) sum += ms->pdpart[w][t];
                ms->npos[j-1][t] += sum;
            }
            for (int idx = t; idx < NPER*ED; idx += HALF){
                int i = idx>>5, k = idx&31;
                float v = 0.f;
                if (i != j){
                    int eL = i*31 + j - (j>i);
                    v = g_e[(ebase+eL)*ED + k];
                }
                *(float2*)&ms->esm2[i][2*k] = make_float2(v, v);
            }
            if (t < NPER){
                int i = t;
                float pix=ms->pos[i][0], piy=ms->pos[i][1], piz=ms->pos[i][2];
                float pjx=ms->pos[j][0], pjy=ms->pos[j][1], pjz=ms->pos[j][2];
                float rx=pjx-pix, ry=pjy-piy, rz=pjz-piz;
                float rr = rx*rx + ry*ry + rz*rz;
                float d  = sqrtf(fmaxf(rr, 1e-6f));
                float inv = 1.f/(1.f + d);
                ms->dbuf[i] = d;
                ms->abuf[i] = pix*pjx + piy*pjy + piz*pjz;
                if (i == j){ rx=0.f; ry=0.f; rz=0.f; }
                ms->rnb[i][0]=rx*inv; ms->rnb[i][1]=ry*inv; ms->rnb[i][2]=rz*inv;
            }
            __syncthreads();

            // [B] hdn = silu(P[i]+Q[j]+e@W1c+d*w1d+a*w1e), packed f32x2
            {
                u64 acc[8];
                const u64 Q2 = __ldg((const u64*)&Qg[j*SD + 2*p]);
#pragma unroll
                for (int r=0;r<8;r++){
                    int i = rq + r;
                    u64 tv = add2(*(const u64*)&ms->P[i][2*p], Q2);
                    tv = fma2(dup2(ms->dbuf[i]), w1d2, tv);
                    tv = fma2(dup2(ms->abuf[i]), w1e2, tv);
                    acc[r] = tv;
                }
#pragma unroll 4
                for (int k2=0;k2<16;k2++){
                    u64 w0 = *(const u64*)&sm->W1c[2*k2  ][2*p];
                    u64 w1 = *(const u64*)&sm->W1c[2*k2+1][2*p];
#pragma unroll
                    for (int r=0;r<8;r++){
                        const ulonglong2 e2 = *(const ulonglong2*)&ms->esm2[rq+r][4*k2];
                        acc[r] = fma2(e2.x, w0, acc[r]);
                        acc[r] = fma2(e2.y, w1, acc[r]);
                    }
                }
                float s0x=0.f, s0y=0.f;
#pragma unroll
                for (int r=0;r<8;r++){
                    int i = rq + r;
                    float hx,hy; unpack2(acc[r],hx,hy);
                    hx = silu_f(hx); hy = silu_f(hy);
                    if (i==j){ hx=0.f; hy=0.f; }
                    *(float2*)&ms->hdn[i][2*p] = make_float2(hx,hy);
                    s0x += hx; s0y += hy;
                }
                // two-stage partial reduce: quarters 0,1 -> s0q[0]; 2,3 -> s0q[1]
                if (q4 == 0 || q4 == 2) *(float2*)&ms->s0q[q4>>1][2*p] = make_float2(s0x,s0y);
                __syncthreads();
                if (q4 == 1 || q4 == 3){
                    float2 prev = *(float2*)&ms->s0q[q4>>1][2*p];
                    *(float2*)&ms->s0q[q4>>1][2*p] = make_float2(prev.x+s0x, prev.y+s0y);
                }
            }
            __syncthreads();

            // [C0] combine partial sums into S0 row j (global scratch)
            if (t < 256)
                S0g[j*SD + t] = ms->s0q[0][t] + ms->s0q[1][t];

            // [C1] pos scalars: t_e = hdn.w2p ; pdpart = sum rn*(t+b2p)
            {
                float pdx=0.f, pdy=0.f, pdz=0.f;
#pragma unroll
                for (int r=0;r<2;r++){
                    int i = wrp + 16*r;
                    float part = 0.f;
#pragma unroll
                    for (int m=0;m<8;m++)
                        part += ms->hdn[i][lane+32*m] * sm->w2p[lane+32*m];
#pragma unroll
                    for (int off=16; off>0; off>>=1)
                        part += __shfl_xor_sync(0xffffffffu, part, off);
                    if (lane==0){
                        float tv = part + b2p;
                        pdx += ms->rnb[i][0]*tv;
                        pdy += ms->rnb[i][1]*tv;
                        pdz += ms->rnb[i][2]*tv;
                    }
                }
                if (lane==0){ ms->pdpart[wrp][0]=pdx; ms->pdpart[wrp][1]=pdy; ms->pdpart[wrp][2]=pdz; }
            }
            // [C2] e update: e += hdn @ W2e + b2e, packed f32x2, smem weights
            {
                const int k = lane;
                const int i0=wrp, i1=wrp+16;
                u64 a0 = 0ULL, a1 = 0ULL;
#pragma unroll 8
                for (int c4=0;c4<64;c4++){
                    ulonglong2 h0 = *(const ulonglong2*)&ms->hdn[i0][4*c4];
                    ulonglong2 h1 = *(const ulonglong2*)&ms->hdn[i1][4*c4];
                    ulonglong2 ww = *(const ulonglong2*)&wt[c4*128];
                    a0 = fma2(h0.x, ww.x, a0); a0 = fma2(h0.y, ww.y, a0);
                    a1 = fma2(h1.x, ww.x, a1); a1 = fma2(h1.y, ww.y, a1);
                }
                float bk = __ldg(&b2[321+k]);
                float x0,y0,x1,y1;
                unpack2(a0,x0,y0); unpack2(a1,x1,y1);
                float v0 = x0+y0+bk, v1 = x1+y1+bk;
                if (i0 != j){
                    int eL = i0*31 + j - (j>i0);
                    g_e[(ebase+eL)*ED + k] = v0 + ms->esm2[i0][2*k];
                }
                if (i1 != j){
                    int eL = i1*31 + j - (j>i1);
                    g_e[(ebase+eL)*ED + k] = v1 + ms->esm2[i1][2*k];
                }
            }
            __syncthreads();
        } // j

        if (t<3){
            float sum=0.f;
#pragma unroll
            for (int w=0;w<16;w++) sum += ms->pdpart[w][t];
            ms->npos[31][t] += sum;
        }
        // s += (S0 @ W2s)/31 + b2s     (S0 broadcast from global scratch)
        {
            float acc[HROWS];
#pragma unroll
            for (int r=0;r<HROWS;r++) acc[r]=0.f;
            for (int kg=0; kg<64; kg++){
                float w0=W2[(4*kg+0)*MSG_OUT+c], w1=W2[(4*kg+1)*MSG_OUT+c];
                float w2v=W2[(4*kg+2)*MSG_OUT+c], w3=W2[(4*kg+3)*MSG_OUT+c];
#pragma unroll
                for (int r=0;r<HROWS;r++){
                    const float4 v = __ldg((const float4*)&S0g[(r0+r)*SD + 4*kg]);
                    acc[r] += v.x*w0 + v.y*w1 + v.z*w2v + v.w*w3;
                }
            }
            float b2s = b2[c];
#pragma unroll
            for (int r=0;r<HROWS;r++)
                sg[(r0+r)*SD + c] += acc[r]*(1.f/31.f) + b2s;
        }
        if (t<96){
            int i = t/3, cc = t%3;
            ms->pos[i][cc] += ms->npos[i][cc]*(1.f/31.f);
        }
        __syncthreads();
    } // layers

    // ------------------------------------------------------------------
    // atoms = silu(s@Wh1+bh1)@Wh2+bh2 ; pos out
    // ------------------------------------------------------------------
    float* Pbuf = &ms->P[0][0];          // 32 x 256 silu buffer
    {
        float acc[HROWS];
#pragma unroll
        for (int r=0;r<HROWS;r++) acc[r]=0.f;
        for (int kg=0; kg<64; kg++){
            float w0=Wh1[(4*kg+0)*SD+c], w1=Wh1[(4*kg+1)*SD+c];
            float w2v=Wh1[(4*kg+2)*SD+c], w3=Wh1[(4*kg+3)*SD+c];
#pragma unroll
            for (int r=0;r<HROWS;r++){
                const float4 v = __ldg((const float4*)&sg[(r0+r)*SD + 4*kg]);
                acc[r] += v.x*w0 + v.y*w1 + v.z*w2v + v.w*w3;
            }
        }
        float bb = bh1[c];
#pragma unroll
        for (int r=0;r<HROWS;r++) Pbuf[(r0+r)*SD + c] = silu_f(acc[r]+bb);
    }
    __syncthreads();
    for (int o = t; o < NPER*16; o += HALF){
        int i = o>>4, cc = o&15;
        float a = bh2[cc];
        for (int k=0;k<SD;k++) a += Pbuf[i*SD + k]*Wh2[k*16+cc];
        outA[(nodeBase+i)*16+cc] = a;
    }
    if (t < 96){
        int i = t/3, cc = t%3;
        outP[(nodeBase+i)*3+cc] = ms->pos[i][cc];
    }
    __syncthreads();

    // ------------------------------------------------------------------
    // bonds: bP = s@We1s (per node); per edge: silu(bP_i+bP_j+e@We1e+d*w288+be1)@We2+be2
    // ------------------------------------------------------------------
    float* bP = &ms->hdn[0][0];          // 32 x 128 (hdn rows 0..15)
    {
        const int c128 = t & 127;
        const int grp  = t >> 7;         // 0..3, rows grp*8 .. grp*8+7
        float acc[8];
#pragma unroll
        for (int r=0;r<8;r++) acc[r]=0.f;
        for (int kg=0; kg<64; kg++){
            float w0=We1[(4*kg+0)*128+c128], w1=We1[(4*kg+1)*128+c128];
            float w2v=We1[(4*kg+2)*128+c128], w3=We1[(4*kg+3)*128+c128];
#pragma unroll
            for (int r=0;r<8;r++){
                const float4 v = __ldg((const float4*)&sg[(grp*8+r)*SD + 4*kg]);
                acc[r] += v.x*w0 + v.y*w1 + v.z*w2v + v.w*w3;
            }
        }
#pragma unroll
        for (int r=0;r<8;r++) bP[(grp*8+r)*128 + c128] = acc[r];
    }
    float* We1e_s = &sm->W1c[0][0];      // 32 x 128 (shared stage)
    for (int idx = tid; idx < 32*128; idx += NTH)
        We1e_s[idx] = We1[(256 + (idx>>7))*128 + (idx&127)];
    __syncthreads();

    float* bh = &ms->hdn[16][0];         // 16 x 128 (hdn rows 16..31)
    float* ebuf = &ms->esm2[0][0];       // 16 x 32 scratch
    {
        const int c128 = t & 127;
        const int grp  = t >> 7;         // 0..3
        const float w288 = We1[288*128 + c128];
        const float bbe  = be1[c128];
        for (int pblk=0; pblk<62; pblk++){
            for (int idx = t; idx < 16*ED; idx += HALF){
                int q = idx>>5, k = idx&31;
                int eL = pblk*16 + q;
                ebuf[q*32+k] = g_e[(ebase+eL)*ED + k];
            }
            if (t < 16){
                int eL = pblk*16 + t;
                int i = eL/31, jj = eL - i*31; int j = jj + (jj>=i);
                float rx=ms->pos[j][0]-ms->pos[i][0];
                float ry=ms->pos[j][1]-ms->pos[i][1];
                float rz=ms->pos[j][2]-ms->pos[i][2];
                ms->dbuf[t] = sqrtf(fmaxf(rx*rx+ry*ry+rz*rz, 1e-6f));
            }
            __syncthreads();
#pragma unroll
            for (int qq=0; qq<4; qq++){
                int q = grp*4 + qq;
                int eL = pblk*16 + q;
                int i = eL/31, jj = eL - i*31; int j = jj + (jj>=i);
                float a = bbe + bP[i*128+c128] + bP[j*128+c128] + ms->dbuf[q]*w288;
#pragma unroll
                for (int kg=0; kg<8; kg++){
                    float4 e4 = ((const float4*)&ebuf[q*32])[kg];
                    a += e4.x*We1e_s[(4*kg+0)*128+c128] + e4.y*We1e_s[(4*kg+1)*128+c128]
                       + e4.z*We1e_s[(4*kg+2)*128+c128] + e4.w*We1e_s[(4*kg+3)*128+c128];
                }
                bh[q*128+c128] = silu_f(a);
            }
            __syncthreads();
            {   // warp wrp (half-local) handles edge wrp of this chunk
                int qq = wrp;
                int eL = pblk*16 + qq;
#pragma unroll
                for (int b=0;b<5;b++){
                    float part = 0.f;
#pragma unroll
                    for (int m=0;m<4;m++){
                        int cc = lane + 32*m;
                        part += bh[qq*128+cc] * We2[cc*5+b];
                    }
#pragma unroll
                    for (int off=16; off>0; off>>=1)
                        part += __shfl_xor_sync(0xffffffffu, part, off);
                    if (lane==0) outB[(ebase+eL)*5+b] = part + be2[b];
                }
            }
            __syncthreads();
        }
    }
}

extern "C" void kernel_launch(void* const* d_in, const int* in_sizes, int n_in,
                              void* d_out, int out_size)
{
    const float* x    = (const float*)d_in[0];
    const float* z    = (const float*)d_in[1];
    const float* rot  = (const float*)d_in[2];
    // d_in[3] edge_index (int64) unused — structure is static block-dense
    const float* eattr= (const float*)d_in[4];
    // d_in[5] batch (int64) unused
    const float* Wam  = (const float*)d_in[6];
    const float* bam  = (const float*)d_in[7];
    const float* Wbm  = (const float*)d_in[8];
    const float* bbm  = (const float*)d_in[9];
    const float* gW1  = (const float*)d_in[10];
    const float* gb1  = (const float*)d_in[11];
    const float* gW2  = (const float*)d_in[12];
    const float* gb2  = (const float*)d_in[13];
    const float* Wh1  = (const float*)d_in[14];
    const float* bh1  = (const float*)d_in[15];
    const float* Wh2  = (const float*)d_in[16];
    const float* bh2  = (const float*)d_in[17];
    const float* We1  = (const float*)d_in[18];
    const float* be1  = (const float*)d_in[19];
    const float* We2  = (const float*)d_in[20];
    const float* be2  = (const float*)d_in[21];

    float* out  = (float*)d_out;
    float* outA = out;                                   // atoms: N x 16
    float* outB = out + (long)NNODE*16;                  // bonds: E x 5
    float* outP = out + (long)NNODE*16 + (long)ETOT*5;   // pos:   N x 3

    prep_kernel<<<160, 256>>>(gW2);

    const size_t shmem = sizeof(SM);
    cudaFuncSetAttribute(dec_kernel, cudaFuncAttributeMaxDynamicSharedMemorySize, (int)shmem);
    dec_kernel<<<NMOL/2, NTH, shmem>>>(x,z,rot,eattr,Wam,bam,Wbm,bbm,
                                       gW1,gb1,gW2,gb2,Wh1,bh1,Wh2,bh2,
                                       We1,be1,We2,be2,outA,outB,outP);
}

// round 7
// speedup vs baseline: 1.0103x; 1.0103x over previous
#include <cuda_runtime.h>
#include <math.h>

#define NMOL 256
#define NPER 32
#define NNODE 8192
#define EPM 992
#define ETOT (NMOL*EPM)
#define SD 256
#define ED 32
#define MSG_IN 546
#define MSG_OUT 353
#define NT 512
#define HROWS 16

typedef unsigned long long u64;

// global scratch
__device__ float g_e[(long)ETOT*ED];                    // edge features (32.5MB, L2)
__device__ __align__(16) float g_w2t [5*64*32*4];       // W2e transposed [l][c4][k][4]
__device__ __align__(16) float g_w1tA[5*8*128*4];       // W1c k-grouped, even cols
__device__ __align__(16) float g_w1tB[5*8*128*4];       // W1c k-grouped, odd cols
__device__ __align__(16) float g_Q [(long)NMOL*NPER*SD];
__device__ __align__(16) float g_P [(long)NMOL*NPER*SD];
__device__ __align__(16) float g_S0[(long)NMOL*NPER*SD];
__device__ __align__(16) float g_s [(long)NMOL*NPER*SD];

struct SM {
    float hdn [NPER][SD];    // 32KB
    float w2s [64*32*4];     // 32KB  [C2] weights
    float w1tA[8*128*4];     // 16KB  [B] weights even cols
    float w1tB[8*128*4];     // 16KB  [B] weights odd cols
    float esm [2][NPER][ED]; // 8KB   double-buffered e rows (non-dup)
    float w2p [SD];          // 1KB
    float pos [NPER][3];
    float npos[NPER][3];
    float dbuf[2][NPER];
    float abuf[2][NPER];
    float rnb [2][NPER][3];
    float pdpart[8][3];
};

__device__ __forceinline__ float silu_f(float v){
    return v * (1.0f / (1.0f + __expf(-v)));
}
__device__ __forceinline__ void unpack2(u64 v, float& x, float& y){
    asm("mov.b64 {%0, %1}, %2;" : "=f"(x), "=f"(y) : "l"(v));
}
__device__ __forceinline__ u64 fma2(u64 a, u64 b, u64 c){
    u64 d; asm("fma.rn.f32x2 %0, %1, %2, %3;" : "=l"(d) : "l"(a), "l"(b), "l"(c)); return d;
}

// prep: weight permutations (run once per launch; deterministic)
__global__ void prep_kernel(const float* __restrict__ gW2, const float* __restrict__ gW1){
    int idx = blockIdx.x*256 + threadIdx.x;
    if (idx < 5*8192){
        int l = idx >> 13; int rem = idx & 8191;
        int c4 = rem >> 7; int rem2 = rem & 127;
        int k = rem2 >> 2; int cc = rem2 & 3;
        g_w2t[idx] = gW2[((long)l*256 + 4*c4 + cc)*MSG_OUT + 321 + k];
        return;
    }
    idx -= 5*8192;
    if (idx < 2*5*4096){
        int half = idx / (5*4096);          // 0=A,1=B
        int r = idx % (5*4096);
        int l = r >> 12; int q = r & 4095;
        int g = q >> 9; int pp = (q >> 2) & 127; int kk = q & 3;
        float v = gW1[((long)l*MSG_IN + 512 + 4*g + kk)*SD + 2*pp + half];
        if (half == 0) g_w1tA[l*4096 + q] = v;
        else           g_w1tB[l*4096 + q] = v;
    }
}

__global__ void __launch_bounds__(NT,2) dec_kernel(
    const float* __restrict__ x,   const float* __restrict__ z,
    const float* __restrict__ rot, const float* __restrict__ eattr,
    const float* __restrict__ Wam, const float* __restrict__ bam,
    const float* __restrict__ Wbm, const float* __restrict__ bbm,
    const float* __restrict__ gW1, const float* __restrict__ gb1,
    const float* __restrict__ gW2, const float* __restrict__ gb2,
    const float* __restrict__ Wh1, const float* __restrict__ bh1,
    const float* __restrict__ Wh2, const float* __restrict__ bh2,
    const float* __restrict__ We1, const float* __restrict__ be1,
    const float* __restrict__ We2, const float* __restrict__ be2,
    float* __restrict__ outA, float* __restrict__ outB, float* __restrict__ outP)
{
    extern __shared__ float smraw[];
    SM* sm = (SM*)smraw;
    const int tid  = threadIdx.x;
    const int lane = tid & 31;
    const int wrp  = tid >> 5;        // 0..15
    const int mol  = blockIdx.x;
    const int nodeBase = mol * NPER;
    const long ebase   = (long)mol * EPM;
    const int c  = tid & 255;         // column for 256-col phases
    const int hh = tid >> 8;
    const int r0 = hh * HROWS;
    const int p  = tid & 127;         // col-pair (2p,2p+1) in [B]
    const int q4 = tid >> 7;          // row quarter
    const int rq = q4 * 8;
    float* Qg  = g_Q  + (size_t)mol*NPER*SD;
    float* Pg  = g_P  + (size_t)mol*NPER*SD;
    float* S0g = g_S0 + (size_t)mol*NPER*SD;
    float* sg  = g_s  + (size_t)mol*NPER*SD;

    // ---------------- Embed ----------------
    {
        float* xz = &sm->hdn[0][0];
        for (int idx = tid; idx < NPER*80; idx += NT){
            int i = idx / 80, k = idx % 80;
            xz[idx] = (k < 16) ? x[(nodeBase+i)*16 + k] : z[(nodeBase+i)*64 + (k-16)];
        }
        __syncthreads();
        float acc[HROWS];
#pragma unroll
        for (int r=0;r<HROWS;r++) acc[r]=0.f;
        for (int kg=0; kg<20; kg++){
            float w0=Wam[(4*kg+0)*259+c], w1=Wam[(4*kg+1)*259+c];
            float w2v=Wam[(4*kg+2)*259+c], w3=Wam[(4*kg+3)*259+c];
#pragma unroll
            for (int r=0;r<HROWS;r++){
                float4 v = ((const float4*)xz)[(r0+r)*20+kg];
                acc[r] += v.x*w0 + v.y*w1 + v.z*w2v + v.w*w3;
            }
        }
        float b = bam[c];
#pragma unroll
        for (int r=0;r<HROWS;r++) sg[(r0+r)*SD + c] = acc[r] + b;
        if (tid < 96){
            int i = tid/3, cc = tid%3;
            float a = bam[256+cc];
            for (int k=0;k<80;k++) a += xz[i*80+k]*Wam[k*259+256+cc];
            sm->npos[i][cc] = a;
        }
        __syncthreads();
        if (tid < 96){
            int i = tid/3, cc = tid%3;
            float pv = 0.f;
#pragma unroll
            for (int q=0;q<3;q++) pv += rot[mol*9 + cc*3 + q]*sm->npos[i][q];
            sm->pos[i][cc] = pv;
        }
    }

    // ---------------- e init ----------------
    for (int idx = tid; idx < EPM*ED; idx += NT){
        int eL = idx >> 5, k = idx & 31;
        const float* ea = &eattr[(ebase+eL)*5];
        float a = bbm[k];
#pragma unroll
        for (int q=0;q<5;q++) a += ea[q]*Wbm[q*ED+k];
        g_e[(ebase+eL)*ED + k] = a;
    }
    __syncthreads();

    // ---------------- 5 layers ----------------
    for (int l=0; l<5; l++){
        const float* W1 = gW1 + (long)l*MSG_IN*SD;
        const float* b1 = gb1 + l*SD;
        const float* W2 = gW2 + (long)l*SD*MSG_OUT;
        const float* b2 = gb2 + l*MSG_OUT;

        // stage weights
        {
            const float4* s2 = (const float4*)(g_w2t + l*8192);
            float4* d2 = (float4*)sm->w2s;
            for (int idx = tid; idx < 2048; idx += NT) d2[idx] = s2[idx];
            const float4* sa = (const float4*)(g_w1tA + l*4096);
            const float4* sb = (const float4*)(g_w1tB + l*4096);
            float4* da = (float4*)sm->w1tA; float4* db = (float4*)sm->w1tB;
            for (int idx = tid; idx < 1024; idx += NT){ da[idx]=sa[idx]; db[idx]=sb[idx]; }
        }
        if (tid < 256) sm->w2p[tid] = W2[tid*MSG_OUT + 320];
        if (tid < 96) sm->npos[tid/3][tid%3] = 0.f;

        // P = s@W1a -> global
        {
            float acc[HROWS];
#pragma unroll
            for (int r=0;r<HROWS;r++) acc[r]=0.f;
            for (int kg=0; kg<64; kg++){
                float wa0=W1[(4*kg+0)*SD+c], wa1=W1[(4*kg+1)*SD+c];
                float wa2=W1[(4*kg+2)*SD+c], wa3=W1[(4*kg+3)*SD+c];
#pragma unroll
                for (int r=0;r<HROWS;r++){
                    const float4 v = __ldg((const float4*)&sg[(r0+r)*SD + 4*kg]);
                    acc[r] += v.x*wa0 + v.y*wa1 + v.z*wa2 + v.w*wa3;
                }
            }
#pragma unroll
            for (int r=0;r<HROWS;r++) Pg[(r0+r)*SD + c]=acc[r];
        }
        // Q = s@W1b + b1 -> global
        {
            float acc[HROWS];
#pragma unroll
            for (int r=0;r<HROWS;r++) acc[r]=0.f;
            for (int kg=0; kg<64; kg++){
                float wb0=W1[(256+4*kg+0)*SD+c], wb1=W1[(256+4*kg+1)*SD+c];
                float wb2=W1[(256+4*kg+2)*SD+c], wb3=W1[(256+4*kg+3)*SD+c];
#pragma unroll
                for (int r=0;r<HROWS;r++){
                    const float4 v = __ldg((const float4*)&sg[(r0+r)*SD + 4*kg]);
                    acc[r] += v.x*wb0 + v.y*wb1 + v.z*wb2 + v.w*wb3;
                }
            }
            float bb = b1[c];
#pragma unroll
            for (int r=0;r<HROWS;r++) Qg[(r0+r)*SD + c] = acc[r]+bb;
        }

        // prologue: stage esm[0] + geometry for j=0
        for (int idx = tid; idx < NPER*ED; idx += NT){
            int i = idx>>5, k = idx&31;
            float v = 0.f;
            if (i != 0) v = g_e[(ebase + i*31 + 0)*ED + k];
            sm->esm[0][i][k] = v;
        }
        if (tid < NPER){
            int i = tid;
            float pix=sm->pos[i][0], piy=sm->pos[i][1], piz=sm->pos[i][2];
            float pjx=sm->pos[0][0], pjy=sm->pos[0][1], pjz=sm->pos[0][2];
            float rx=pjx-pix, ry=pjy-piy, rz=pjz-piz;
            float d = sqrtf(fmaxf(rx*rx+ry*ry+rz*rz, 1e-6f));
            float inv = 1.f/(1.f+d);
            sm->dbuf[0][i]=d; sm->abuf[0][i]=pix*pjx+piy*pjy+piz*pjz;
            if (i==0){rx=0;ry=0;rz=0;}
            sm->rnb[0][i][0]=rx*inv; sm->rnb[0][i][1]=ry*inv; sm->rnb[0][i][2]=rz*inv;
        }
        __syncthreads();

        const float w1dx = __ldg(&W1[544*SD + 2*p]);
        const float w1dy = __ldg(&W1[544*SD + 2*p+1]);
        const float w1ex = __ldg(&W1[545*SD + 2*p]);
        const float w1ey = __ldg(&W1[545*SD + 2*p+1]);
        const float b2p  = __ldg(&b2[320]);

        for (int j=0; j<NPER; j++){
            const int buf = j & 1, nbuf = buf ^ 1;

            // ---- phase 1: [B] + pdpart fold ----
            if (j>0 && tid<3){
                float sum=0.f;
#pragma unroll
                for (int w=0;w<8;w++) sum += sm->pdpart[w][tid];
                sm->npos[j-1][tid] += sum;
            }
            {
                u64 acc0[8], acc1[8];
#pragma unroll
                for (int r=0;r<8;r++){ acc0[r]=0ULL; acc1[r]=0ULL; }
#pragma unroll
                for (int g=0;g<8;g++){
                    ulonglong2 WA = *(const ulonglong2*)&sm->w1tA[(g*128+p)*4];
                    ulonglong2 WB = *(const ulonglong2*)&sm->w1tB[(g*128+p)*4];
#pragma unroll
                    for (int r=0;r<8;r++){
                        ulonglong2 E = *(const ulonglong2*)&sm->esm[buf][rq+r][4*g];
                        acc0[r]=fma2(E.x,WA.x,acc0[r]); acc0[r]=fma2(E.y,WA.y,acc0[r]);
                        acc1[r]=fma2(E.x,WB.x,acc1[r]); acc1[r]=fma2(E.y,WB.y,acc1[r]);
                    }
                }
                // epilogue (P/Q loads issued here; consumed after arrival)
                u64 pv[8];
#pragma unroll
                for (int r=0;r<8;r++) pv[r] = __ldg((const u64*)&Pg[(rq+r)*SD + 2*p]);
                u64 qv = __ldg((const u64*)&Qg[j*SD + 2*p]);
                float qx,qy; unpack2(qv,qx,qy);
#pragma unroll
                for (int r=0;r<8;r++){
                    int i = rq+r;
                    float d = sm->dbuf[buf][i], a = sm->abuf[buf][i];
                    float px,py; unpack2(pv[r],px,py);
                    float a0x,a0y,a1x,a1y;
                    unpack2(acc0[r],a0x,a0y); unpack2(acc1[r],a1x,a1y);
                    float h0 = a0x+a0y + px + qx + d*w1dx + a*w1ex;
                    float h1 = a1x+a1y + py + qy + d*w1dy + a*w1ey;
                    h0 = silu_f(h0); h1 = silu_f(h1);
                    if (i==j){ h0=0.f; h1=0.f; }
                    *(float2*)&sm->hdn[i][2*p] = make_float2(h0,h1);
                }
            }
            __syncthreads();

            // ---- phase 2: warp-specialized ----
            if (wrp < 8){
                // [C2] e update: rows {wrp, wrp+8, wrp+16, wrp+24}, k=lane
                const float* wt = sm->w2s + lane*4;
                u64 a[4] = {0ULL,0ULL,0ULL,0ULL};
#pragma unroll 8
                for (int c4=0;c4<64;c4++){
                    ulonglong2 ww = *(const ulonglong2*)&wt[c4*128];
#pragma unroll
                    for (int rr=0;rr<4;rr++){
                        ulonglong2 h = *(const ulonglong2*)&sm->hdn[wrp+8*rr][4*c4];
                        a[rr]=fma2(h.x,ww.x,a[rr]); a[rr]=fma2(h.y,ww.y,a[rr]);
                    }
                }
                float bk = __ldg(&b2[321+lane]);
#pragma unroll
                for (int rr=0;rr<4;rr++){
                    int i = wrp + 8*rr;
                    if (i != j){
                        float ax,ay; unpack2(a[rr],ax,ay);
                        int eL = i*31 + j - (j>i);
                        g_e[(ebase+eL)*ED + lane] = ax+ay+bk + sm->esm[buf][i][lane];
                    }
                }
            } else {
                const int v = wrp - 8;
                // [C1] pos scalars: rows 4v..4v+3
                {
                    float pdx=0.f, pdy=0.f, pdz=0.f;
#pragma unroll
                    for (int rr=0;rr<4;rr++){
                        int i = v*4+rr;
                        float part = 0.f;
#pragma unroll
                        for (int m=0;m<8;m++)
                            part += sm->hdn[i][lane+32*m] * sm->w2p[lane+32*m];
#pragma unroll
                        for (int off=16; off>0; off>>=1)
                            part += __shfl_xor_sync(0xffffffffu, part, off);
                        if (lane==0){
                            float t = part + b2p;
                            pdx += sm->rnb[buf][i][0]*t;
                            pdy += sm->rnb[buf][i][1]*t;
                            pdz += sm->rnb[buf][i][2]*t;
                        }
                    }
                    if (lane==0){ sm->pdpart[v][0]=pdx; sm->pdpart[v][1]=pdy; sm->pdpart[v][2]=pdz; }
                }
                // S0 row j: column sums of hdn
                {
                    int gt = tid - 256;      // 0..255
                    float s0=0.f, s1=0.f;
#pragma unroll
                    for (int i=0;i<32;i+=2){ s0 += sm->hdn[i][gt]; s1 += sm->hdn[i+1][gt]; }
                    S0g[j*SD + gt] = s0 + s1;
                }
                // stage esm/geometry for j+1
                if (j < 31){
                    int gt = tid - 256;
                    for (int idx = gt; idx < NPER*ED; idx += 256){
                        int i = idx>>5, k = idx&31;
                        float vv = 0.f;
                        if (i != j+1) vv = g_e[(ebase + i*31 + (j+1) - ((j+1)>i))*ED + k];
                        sm->esm[nbuf][i][k] = vv;
                    }
                    if (gt < NPER){
                        int i = gt;
                        float pix=sm->pos[i][0], piy=sm->pos[i][1], piz=sm->pos[i][2];
                        float pjx=sm->pos[j+1][0], pjy=sm->pos[j+1][1], pjz=sm->pos[j+1][2];
                        float rx=pjx-pix, ry=pjy-piy, rz=pjz-piz;
                        float d = sqrtf(fmaxf(rx*rx+ry*ry+rz*rz, 1e-6f));
                        float inv = 1.f/(1.f+d);
                        sm->dbuf[nbuf][i]=d; sm->abuf[nbuf][i]=pix*pjx+piy*pjy+piz*pjz;
                        if (i==j+1){rx=0;ry=0;rz=0;}
                        sm->rnb[nbuf][i][0]=rx*inv; sm->rnb[nbuf][i][1]=ry*inv; sm->rnb[nbuf][i][2]=rz*inv;
                    }
                }
            }
            __syncthreads();
        } // j

        if (tid<3){
            float sum=0.f;
#pragma unroll
            for (int w=0;w<8;w++) sum += sm->pdpart[w][tid];
            sm->npos[31][tid] += sum;
        }
        // s += (S0 @ W2s)/31 + b2s
        {
            float acc[HROWS];
#pragma unroll
            for (int r=0;r<HROWS;r++) acc[r]=0.f;
            for (int kg=0; kg<64; kg++){
                float w0=W2[(4*kg+0)*MSG_OUT+c], w1=W2[(4*kg+1)*MSG_OUT+c];
                float w2v=W2[(4*kg+2)*MSG_OUT+c], w3=W2[(4*kg+3)*MSG_OUT+c];
#pragma unroll
                for (int r=0;r<HROWS;r++){
                    const float4 v = __ldg((const float4*)&S0g[(r0+r)*SD + 4*kg]);
                    acc[r] += v.x*w0 + v.y*w1 + v.z*w2v + v.w*w3;
                }
            }
            float b2s = b2[c];
#pragma unroll
            for (int r=0;r<HROWS;r++)
                sg[(r0+r)*SD + c] += acc[r]*(1.f/31.f) + b2s;
        }
        if (tid<96){
            int i = tid/3, cc = tid%3;
            sm->pos[i][cc] += sm->npos[i][cc]*(1.f/31.f);
        }
        __syncthreads();
    } // layers

    // ---------------- atoms + pos out ----------------
    float* Pbuf = sm->w2s;               // 32KB scratch
    {
        float acc[HROWS];
#pragma unroll
        for (int r=0;r<HROWS;r++) acc[r]=0.f;
        for (int kg=0; kg<64; kg++){
            float w0=Wh1[(4*kg+0)*SD+c], w1=Wh1[(4*kg+1)*SD+c];
            float w2v=Wh1[(4*kg+2)*SD+c], w3=Wh1[(4*kg+3)*SD+c];
#pragma unroll
            for (int r=0;r<HROWS;r++){
                const float4 v = __ldg((const float4*)&sg[(r0+r)*SD + 4*kg]);
                acc[r] += v.x*w0 + v.y*w1 + v.z*w2v + v.w*w3;
            }
        }
        float bb = bh1[c];
#pragma unroll
        for (int r=0;r<HROWS;r++) Pbuf[(r0+r)*SD + c] = silu_f(acc[r]+bb);
    }
    __syncthreads();
    for (int o = tid; o < NPER*16; o += NT){
        int i = o>>4, cc = o&15;
        float a = bh2[cc];
        for (int k=0;k<SD;k++) a += Pbuf[i*SD + k]*Wh2[k*16+cc];
        outA[(nodeBase+i)*16+cc] = a;
    }
    if (tid < 96){
        int i = tid/3, cc = tid%3;
        outP[(nodeBase+i)*3+cc] = sm->pos[i][cc];
    }
    __syncthreads();

    // ---------------- bonds ----------------
    float* bP = &sm->hdn[0][0];          // 32 x 128 (hdn rows 0..15)
    {
        const int c128 = tid & 127;
        const int grp  = tid >> 7;
        float acc[8];
#pragma unroll
        for (int r=0;r<8;r++) acc[r]=0.f;
        for (int kg=0; kg<64; kg++){
            float w0=We1[(4*kg+0)*128+c128], w1=We1[(4*kg+1)*128+c128];
            float w2v=We1[(4*kg+2)*128+c128], w3=We1[(4*kg+3)*128+c128];
#pragma unroll
            for (int r=0;r<8;r++){
                const float4 v = __ldg((const float4*)&sg[(grp*8+r)*SD + 4*kg]);
                acc[r] += v.x*w0 + v.y*w1 + v.z*w2v + v.w*w3;
            }
        }
#pragma unroll
        for (int r=0;r<8;r++) bP[(grp*8+r)*128 + c128] = acc[r];
    }
    float* We1e_s = &sm->hdn[16][0];     // 32 x 128
    for (int idx = tid; idx < 32*128; idx += NT)
        We1e_s[idx] = We1[(256 + (idx>>7))*128 + (idx&127)];
    __syncthreads();

    float* bh = sm->w1tA;                // 16 x 128 (8KB)
    float* ebuf = &sm->esm[0][0][0];     // 16 x 32
    {
        const int c128 = tid & 127;
        const int grp  = tid >> 7;
        const float w288 = We1[288*128 + c128];
        const float bbe  = be1[c128];
        for (int pblk=0; pblk<62; pblk++){
            for (int idx = tid; idx < 16*ED; idx += NT){
                int q = idx>>5, k = idx&31;
                int eL = pblk*16 + q;
                ebuf[q*32+k] = g_e[(ebase+eL)*ED + k];
            }
            if (tid < 16){
                int eL = pblk*16 + tid;
                int i = eL/31, jj = eL - i*31; int j = jj + (jj>=i);
                float rx=sm->pos[j][0]-sm->pos[i][0];
                float ry=sm->pos[j][1]-sm->pos[i][1];
                float rz=sm->pos[j][2]-sm->pos[i][2];
                sm->dbuf[0][tid] = sqrtf(fmaxf(rx*rx+ry*ry+rz*rz, 1e-6f));
            }
            __syncthreads();
#pragma unroll
            for (int qq=0; qq<4; qq++){
                int q = grp*4 + qq;
                int eL = pblk*16 + q;
                int i = eL/31, jj = eL - i*31; int j = jj + (jj>=i);
                float a = bbe + bP[i*128+c128] + bP[j*128+c128] + sm->dbuf[0][q]*w288;
#pragma unroll
                for (int kg=0; kg<8; kg++){
                    float4 e4 = ((const float4*)&ebuf[q*32])[kg];
                    a += e4.x*We1e_s[(4*kg+0)*128+c128] + e4.y*We1e_s[(4*kg+1)*128+c128]
                       + e4.z*We1e_s[(4*kg+2)*128+c128] + e4.w*We1e_s[(4*kg+3)*128+c128];
                }
                bh[q*128+c128] = silu_f(a);
            }
            __syncthreads();
            {
                int qq = wrp;
                int eL = pblk*16 + qq;
#pragma unroll
                for (int b=0;b<5;b++){
                    float part = 0.f;
#pragma unroll
                    for (int m=0;m<4;m++){
                        int cc = lane + 32*m;
                        part += bh[qq*128+cc] * We2[cc*5+b];
                    }
#pragma unroll
                    for (int off=16; off>0; off>>=1)
                        part += __shfl_xor_sync(0xffffffffu, part, off);
                    if (lane==0) outB[(ebase+eL)*5+b] = part + be2[b];
                }
            }
            __syncthreads();
        }
    }
}

extern "C" void kernel_launch(void* const* d_in, const int* in_sizes, int n_in,
                              void* d_out, int out_size)
{
    const float* x    = (const float*)d_in[0];
    const float* z    = (const float*)d_in[1];
    const float* rot  = (const float*)d_in[2];
    const float* eattr= (const float*)d_in[4];
    const float* Wam  = (const float*)d_in[6];
    const float* bam  = (const float*)d_in[7];
    const float* Wbm  = (const float*)d_in[8];
    const float* bbm  = (const float*)d_in[9];
    const float* gW1  = (const float*)d_in[10];
    const float* gb1  = (const float*)d_in[11];
    const float* gW2  = (const float*)d_in[12];
    const float* gb2  = (const float*)d_in[13];
    const float* Wh1  = (const float*)d_in[14];
    const float* bh1  = (const float*)d_in[15];
    const float* Wh2  = (const float*)d_in[16];
    const float* bh2  = (const float*)d_in[17];
    const float* We1  = (const float*)d_in[18];
    const float* be1  = (const float*)d_in[19];
    const float* We2  = (const float*)d_in[20];
    const float* be2  = (const float*)d_in[21];

    float* out  = (float*)d_out;
    float* outA = out;
    float* outB = out + (long)NNODE*16;
    float* outP = out + (long)NNODE*16 + (long)ETOT*5;

    prep_kernel<<<320, 256>>>(gW2, gW1);

    const size_t shmem = sizeof(SM);
    cudaFuncSetAttribute(dec_kernel, cudaFuncAttributeMaxDynamicSharedMemorySize, (int)shmem);
    dec_kernel<<<NMOL, NT, shmem>>>(x,z,rot,eattr,Wam,bam,Wbm,bbm,
                                    gW1,gb1,gW2,gb2,Wh1,bh1,Wh2,bh2,
                                    We1,be1,We2,be2,outA,outB,outP);
}

// round 8
// speedup vs baseline: 1.0142x; 1.0038x over previous
#include <cuda_runtime.h>
#include <math.h>

#define NMOL 256
#define NPER 32
#define NNODE 8192
#define EPM 992                  // 32*31 edges per molecule
#define ETOT (NMOL*EPM)          // 253952
#define SD 256
#define ED 32
#define MSG_IN 546
#define MSG_OUT 353
#define NT 512                   // threads per CTA (16 warps)
#define HROWS 16                 // rows per thread-half (for 256-col sections)

typedef unsigned long long u64;

// global scratch (sanctioned __device__ arrays)
__device__ float g_e[(long)ETOT*ED];                    // edge features (32.5MB, L2)
__device__ __align__(16) float g_w2t[5*64*32*4];        // transposed W2e  [l][c4][k][4]
__device__ __align__(16) float g_Q [(long)NMOL*NPER*SD];// per-layer Q rows
__device__ __align__(16) float g_S0[(long)NMOL*NPER*SD];// per-layer S0 rows
__device__ __align__(16) float g_s [(long)NMOL*NPER*SD];// node scalar features

struct SM {
    float P  [NPER][SD];   // s @ W1a  (per-src part)         32KB
    float hdn[NPER][SD];   // hidden activations, tgt j       32KB
    float w2s[64*32*4];    // [C2] weights (staged per layer) 32KB
    float esm2[NPER][2*ED];// e rows for tgt j, DUPLICATED     8KB
    float s0q[4][SD];      // per-quarter partial sums         4KB
    float pos [NPER][3];
    float npos[NPER][3];
    float dbuf[NPER];
    float abuf[NPER];
    float rnb [NPER][3];
    float w2p [SD];
    float pdpart[16][3];
};

__device__ __forceinline__ float silu_f(float v){
    return v * (1.0f / (1.0f + __expf(-v)));
}
__device__ __forceinline__ u64 pack2(float x, float y){
    u64 r; asm("mov.b64 %0, {%1, %2};" : "=l"(r) : "f"(x), "f"(y)); return r;
}
__device__ __forceinline__ void unpack2(u64 v, float& x, float& y){
    asm("mov.b64 {%0, %1}, %2;" : "=f"(x), "=f"(y) : "l"(v));
}
__device__ __forceinline__ u64 fma2(u64 a, u64 b, u64 c){
    u64 d; asm("fma.rn.f32x2 %0, %1, %2, %3;" : "=l"(d) : "l"(a), "l"(b), "l"(c)); return d;
}
__device__ __forceinline__ u64 add2(u64 a, u64 b){
    u64 d; asm("add.rn.f32x2 %0, %1, %2;" : "=l"(d) : "l"(a), "l"(b)); return d;
}
__device__ __forceinline__ u64 dup2(float x){ return pack2(x,x); }

// prep: g_w2t[l*8192 + c4*128 + k*4 + cc] = gW2[(l*256+4*c4+cc)*353 + 321 + k]
__global__ void prep_kernel(const float* __restrict__ gW2){
    int idx = blockIdx.x*256 + threadIdx.x;
    if (idx >= 5*8192) return;
    int l = idx >> 13; int rem = idx & 8191;
    int c4 = rem >> 7; int rem2 = rem & 127;
    int k = rem2 >> 2; int cc = rem2 & 3;
    g_w2t[idx] = gW2[((long)l*256 + 4*c4 + cc)*MSG_OUT + 321 + k];
}

__global__ void __launch_bounds__(NT,2) dec_kernel(
    const float* __restrict__ x,   const float* __restrict__ z,
    const float* __restrict__ rot, const float* __restrict__ eattr,
    const float* __restrict__ Wam, const float* __restrict__ bam,
    const float* __restrict__ Wbm, const float* __restrict__ bbm,
    const float* __restrict__ gW1, const float* __restrict__ gb1,
    const float* __restrict__ gW2, const float* __restrict__ gb2,
    const float* __restrict__ Wh1, const float* __restrict__ bh1,
    const float* __restrict__ Wh2, const float* __restrict__ bh2,
    const float* __restrict__ We1, const float* __restrict__ be1,
    const float* __restrict__ We2, const float* __restrict__ be2,
    float* __restrict__ outA, float* __restrict__ outB, float* __restrict__ outP)
{
    extern __shared__ float smraw[];
    SM* sm = (SM*)smraw;
    const int tid  = threadIdx.x;
    const int lane = tid & 31;
    const int wrp  = tid >> 5;        // 0..15
    const int mol  = blockIdx.x;
    const int nodeBase = mol * NPER;
    const long ebase   = (long)mol * EPM;
    const int c  = tid & 255;         // column (0..255) for 256-col sections
    const int hh = tid >> 8;          // row-half (0/1)
    const int r0 = hh * HROWS;
    const int p  = tid & 127;         // col-pair index (cols 2p, 2p+1) for [B]
    const int q4 = tid >> 7;          // row-quarter (0..3) for [B]
    const int rq = q4 * 8;            // first row of this quarter
    float* Qg  = g_Q  + (size_t)mol*NPER*SD;
    float* S0g = g_S0 + (size_t)mol*NPER*SD;
    float* sg  = g_s  + (size_t)mol*NPER*SD;

    // ------------------------------------------------------------------
    // Embed: h = [x,z] @ Wam + bam ; s = h[:,:256]; pos = rot @ h[:,256:259]
    // ------------------------------------------------------------------
    {
        float* xz = &sm->hdn[0][0];                 // reuse: 32*80 floats
        for (int idx = tid; idx < NPER*80; idx += NT){
            int i = idx / 80, k = idx % 80;
            xz[idx] = (k < 16) ? x[(nodeBase+i)*16 + k]
                               : z[(nodeBase+i)*64 + (k-16)];
        }
        __syncthreads();
        float acc[HROWS];
#pragma unroll
        for (int r=0;r<HROWS;r++) acc[r]=0.f;
        for (int kg=0; kg<20; kg++){
            float w0=Wam[(4*kg+0)*259+c], w1=Wam[(4*kg+1)*259+c];
            float w2v=Wam[(4*kg+2)*259+c], w3=Wam[(4*kg+3)*259+c];
#pragma unroll
            for (int r=0;r<HROWS;r++){
                float4 v = ((const float4*)xz)[(r0+r)*20+kg];
                acc[r] += v.x*w0 + v.y*w1 + v.z*w2v + v.w*w3;
            }
        }
        float b = bam[c];
#pragma unroll
        for (int r=0;r<HROWS;r++) sg[(r0+r)*SD + c] = acc[r] + b;
        if (tid < 96){                                // pos3 into npos (tmp)
            int i = tid/3, cc = tid%3;
            float a = bam[256+cc];
            for (int k=0;k<80;k++) a += xz[i*80+k]*Wam[k*259+256+cc];
            sm->npos[i][cc] = a;
        }
        __syncthreads();
        if (tid < 96){
            int i = tid/3, cc = tid%3;
            float pv = 0.f;
#pragma unroll
            for (int q=0;q<3;q++) pv += rot[mol*9 + cc*3 + q]*sm->npos[i][q];
            sm->pos[i][cc] = pv;
        }
    }

    // ------------------------------------------------------------------
    // e init: e = edge_attr @ Wbm + bbm   (into global scratch)
    // ------------------------------------------------------------------
    for (int idx = tid; idx < EPM*ED; idx += NT){
        int eL = idx >> 5, k = idx & 31;
        const float* ea = &eattr[(ebase+eL)*5];
        float a = bbm[k];
#pragma unroll
        for (int q=0;q<5;q++) a += ea[q]*Wbm[q*ED+k];
        g_e[(ebase+eL)*ED + k] = a;
    }
    __syncthreads();

    // ------------------------------------------------------------------
    // 5 message-passing layers
    // ------------------------------------------------------------------
    for (int l=0; l<5; l++){
        const float* W1 = gW1 + (long)l*MSG_IN*SD;
        const float* b1 = gb1 + l*SD;
        const float* W2 = gW2 + (long)l*SD*MSG_OUT;
        const float* b2 = gb2 + l*MSG_OUT;

        // stage [C2] weights into SMEM; w2p; zero npos
        {
            const float4* src = (const float4*)(g_w2t + l*8192);
            float4* dst = (float4*)sm->w2s;
            for (int idx = tid; idx < 2048; idx += NT) dst[idx] = src[idx];
        }
        if (tid < 256) sm->w2p[tid] = W2[tid*MSG_OUT + 320];
        if (tid < 96) sm->npos[tid/3][tid%3] = 0.f;

        // P = s@W1a (pass 1, 16 accs) -> SMEM
        {
            float acc[HROWS];
#pragma unroll
            for (int r=0;r<HROWS;r++) acc[r]=0.f;
            for (int kg=0; kg<64; kg++){
                float wa0=W1[(4*kg+0)*SD+c], wa1=W1[(4*kg+1)*SD+c];
                float wa2=W1[(4*kg+2)*SD+c], wa3=W1[(4*kg+3)*SD+c];
#pragma unroll
                for (int r=0;r<HROWS;r++){
                    const float4 v = __ldg((const float4*)&sg[(r0+r)*SD + 4*kg]);
                    acc[r] += v.x*wa0 + v.y*wa1 + v.z*wa2 + v.w*wa3;
                }
            }
#pragma unroll
            for (int r=0;r<HROWS;r++) sm->P[r0+r][c]=acc[r];
        }
        // Q = s@W1b + b1 (pass 2, 16 accs) -> global scratch
        {
            float acc[HROWS];
#pragma unroll
            for (int r=0;r<HROWS;r++) acc[r]=0.f;
            for (int kg=0; kg<64; kg++){
                float wb0=W1[(256+4*kg+0)*SD+c], wb1=W1[(256+4*kg+1)*SD+c];
                float wb2=W1[(256+4*kg+2)*SD+c], wb3=W1[(256+4*kg+3)*SD+c];
#pragma unroll
                for (int r=0;r<HROWS;r++){
                    const float4 v = __ldg((const float4*)&sg[(r0+r)*SD + 4*kg]);
                    acc[r] += v.x*wb0 + v.y*wb1 + v.z*wb2 + v.w*wb3;
                }
            }
            float bb = b1[c];
#pragma unroll
            for (int r=0;r<HROWS;r++) Qg[(r0+r)*SD + c] = acc[r]+bb;
        }
        __syncthreads();

        // per-layer packed constants for [B] (col-pair 2p,2p+1)
        const u64 w1d2 = __ldg((const u64*)&W1[544*SD + 2*p]);
        const u64 w1e2 = __ldg((const u64*)&W1[545*SD + 2*p]);
        const float b2p = __ldg(&b2[320]);
        const float* wt  = sm->w2s + lane*4;           // for [C2] (SMEM)
        const float* W1c = W1 + 512*SD;                // e-part of W1 (global)

        for (int j=0; j<NPER; j++){
            // [A] fold prev pdpart into npos; stage e rows (duplicated) + geometry
            if (j>0 && tid<3){
                float sum=0.f;
#pragma unroll
                for (int w=0;w<16;w++) sum += sm->pdpart[w][tid];
                sm->npos[j-1][tid] += sum;
            }
            for (int idx = tid; idx < NPER*ED; idx += NT){
                int i = idx>>5, k = idx&31;
                float v = 0.f;
                if (i != j){
                    int eL = i*31 + j - (j>i);
                    v = g_e[(ebase+eL)*ED + k];
                }
                *(float2*)&sm->esm2[i][2*k] = make_float2(v, v);
            }
            if (tid < NPER){
                int i = tid;
                float pix=sm->pos[i][0], piy=sm->pos[i][1], piz=sm->pos[i][2];
                float pjx=sm->pos[j][0], pjy=sm->pos[j][1], pjz=sm->pos[j][2];
                float rx=pjx-pix, ry=pjy-piy, rz=pjz-piz;
                float rr = rx*rx + ry*ry + rz*rz;
                float d  = sqrtf(fmaxf(rr, 1e-6f));
                float inv = 1.f/(1.f + d);
                sm->dbuf[i] = d;
                sm->abuf[i] = pix*pjx + piy*pjy + piz*pjz;
                if (i == j){ rx=0.f; ry=0.f; rz=0.f; }
                sm->rnb[i][0]=rx*inv; sm->rnb[i][1]=ry*inv; sm->rnb[i][2]=rz*inv;
            }
            __syncthreads();

            // [B] hdn = silu(P[i]+Q[j]+e@W1c+d*w1d+a*w1e), packed f32x2
            {
                u64 acc[8];
                const u64 Q2 = __ldg((const u64*)&Qg[j*SD + 2*p]);
#pragma unroll
                for (int r=0;r<8;r++){
                    int i = rq + r;
                    u64 t = add2(*(const u64*)&sm->P[i][2*p], Q2);
                    t = fma2(dup2(sm->dbuf[i]), w1d2, t);
                    t = fma2(dup2(sm->abuf[i]), w1e2, t);
                    acc[r] = t;
                }
#pragma unroll 4
                for (int k2=0;k2<16;k2++){
                    u64 w0 = __ldg((const u64*)&W1c[(2*k2  )*SD + 2*p]);
                    u64 w1 = __ldg((const u64*)&W1c[(2*k2+1)*SD + 2*p]);
#pragma unroll
                    for (int r=0;r<8;r++){
                        const ulonglong2 e2 = *(const ulonglong2*)&sm->esm2[rq+r][4*k2];
                        acc[r] = fma2(e2.x, w0, acc[r]);
                        acc[r] = fma2(e2.y, w1, acc[r]);
                    }
                }
                float s0x=0.f, s0y=0.f;
#pragma unroll
                for (int r=0;r<8;r++){
                    int i = rq + r;
                    float hx,hy; unpack2(acc[r],hx,hy);
                    hx = silu_f(hx); hy = silu_f(hy);
                    if (i==j){ hx=0.f; hy=0.f; }
                    *(float2*)&sm->hdn[i][2*p] = make_float2(hx,hy);
                    s0x += hx; s0y += hy;
                }
                *(float2*)&sm->s0q[q4][2*p] = make_float2(s0x,s0y);
            }
            __syncthreads();

            // [C0] combine partial sums into S0 row j (global scratch)
            if (tid < 256)
                S0g[j*SD + tid] = sm->s0q[0][tid] + sm->s0q[1][tid]
                                + sm->s0q[2][tid] + sm->s0q[3][tid];

            // [C1] pos scalars: t_e = hdn.w2p ; pdpart = sum rn*(t+b2p)
            {
                float pdx=0.f, pdy=0.f, pdz=0.f;
#pragma unroll
                for (int r=0;r<2;r++){
                    int i = wrp + 16*r;
                    float part = 0.f;
#pragma unroll
                    for (int m=0;m<8;m++)
                        part += sm->hdn[i][lane+32*m] * sm->w2p[lane+32*m];
#pragma unroll
                    for (int off=16; off>0; off>>=1)
                        part += __shfl_xor_sync(0xffffffffu, part, off);
                    if (lane==0){
                        float t = part + b2p;
                        pdx += sm->rnb[i][0]*t;
                        pdy += sm->rnb[i][1]*t;
                        pdz += sm->rnb[i][2]*t;
                    }
                }
                if (lane==0){ sm->pdpart[wrp][0]=pdx; sm->pdpart[wrp][1]=pdy; sm->pdpart[wrp][2]=pdz; }
            }
            // [C2] e update: e += hdn @ W2e + b2e, packed f32x2, SMEM weights
            {
                const int k = lane;
                const int i0=wrp, i1=wrp+16;
                u64 a0 = 0ULL, a1 = 0ULL;
#pragma unroll 8
                for (int c4=0;c4<64;c4++){
                    ulonglong2 h0 = *(const ulonglong2*)&sm->hdn[i0][4*c4];
                    ulonglong2 h1 = *(const ulonglong2*)&sm->hdn[i1][4*c4];
                    ulonglong2 ww = *(const ulonglong2*)&wt[c4*128];
                    a0 = fma2(h0.x, ww.x, a0); a0 = fma2(h0.y, ww.y, a0);
                    a1 = fma2(h1.x, ww.x, a1); a1 = fma2(h1.y, ww.y, a1);
                }
                float bk = __ldg(&b2[321+k]);
                float x0,y0,x1,y1;
                unpack2(a0,x0,y0); unpack2(a1,x1,y1);
                float v0 = x0+y0+bk, v1 = x1+y1+bk;
                if (i0 != j){
                    int eL = i0*31 + j - (j>i0);
                    g_e[(ebase+eL)*ED + k] = v0 + sm->esm2[i0][2*k];
                }
                if (i1 != j){
                    int eL = i1*31 + j - (j>i1);
                    g_e[(ebase+eL)*ED + k] = v1 + sm->esm2[i1][2*k];
                }
            }
            __syncthreads();
        } // j

        if (tid<3){
            float sum=0.f;
#pragma unroll
            for (int w=0;w<16;w++) sum += sm->pdpart[w][tid];
            sm->npos[31][tid] += sum;
        }
        // s += (S0 @ W2s)/31 + b2s     (S0 broadcast from global scratch)
        {
            float acc[HROWS];
#pragma unroll
            for (int r=0;r<HROWS;r++) acc[r]=0.f;
            for (int kg=0; kg<64; kg++){
                float w0=W2[(4*kg+0)*MSG_OUT+c], w1=W2[(4*kg+1)*MSG_OUT+c];
                float w2v=W2[(4*kg+2)*MSG_OUT+c], w3=W2[(4*kg+3)*MSG_OUT+c];
#pragma unroll
                for (int r=0;r<HROWS;r++){
                    const float4 v = __ldg((const float4*)&S0g[(r0+r)*SD + 4*kg]);
                    acc[r] += v.x*w0 + v.y*w1 + v.z*w2v + v.w*w3;
                }
            }
            float b2s = b2[c];
#pragma unroll
            for (int r=0;r<HROWS;r++)
                sg[(r0+r)*SD + c] += acc[r]*(1.f/31.f) + b2s;
        }
        if (tid<96){
            int i = tid/3, cc = tid%3;
            sm->pos[i][cc] += sm->npos[i][cc]*(1.f/31.f);
        }
        __syncthreads();
    } // layers

    // ------------------------------------------------------------------
    // atoms = silu(s@Wh1+bh1)@Wh2+bh2 ; pos out
    // ------------------------------------------------------------------
    {
        float acc[HROWS];
#pragma unroll
        for (int r=0;r<HROWS;r++) acc[r]=0.f;
        for (int kg=0; kg<64; kg++){
            float w0=Wh1[(4*kg+0)*SD+c], w1=Wh1[(4*kg+1)*SD+c];
            float w2v=Wh1[(4*kg+2)*SD+c], w3=Wh1[(4*kg+3)*SD+c];
#pragma unroll
            for (int r=0;r<HROWS;r++){
                const float4 v = __ldg((const float4*)&sg[(r0+r)*SD + 4*kg]);
                acc[r] += v.x*w0 + v.y*w1 + v.z*w2v + v.w*w3;
            }
        }
        float bb = bh1[c];
#pragma unroll
        for (int r=0;r<HROWS;r++) sm->P[r0+r][c] = silu_f(acc[r]+bb);
    }
    __syncthreads();
    for (int o = tid; o < NPER*16; o += NT){
        int i = o>>4, cc = o&15;
        float a = bh2[cc];
        for (int k=0;k<SD;k++) a += sm->P[i][k]*Wh2[k*16+cc];
        outA[(nodeBase+i)*16+cc] = a;
    }
    if (tid < 96){
        int i = tid/3, cc = tid%3;
        outP[(nodeBase+i)*3+cc] = sm->pos[i][cc];
    }
    __syncthreads();

    // ------------------------------------------------------------------
    // bonds: bP = s@We1s (per node); per edge: silu(bP_i+bP_j+e@We1e+d*w288+be1)@We2+be2
    // ------------------------------------------------------------------
    float* bP = &sm->hdn[0][0];          // 32 x 128 (hdn rows 0..15)
    {
        const int c128 = tid & 127;
        const int grp  = tid >> 7;       // 0..3, rows grp*8 .. grp*8+7
        float acc[8];
#pragma unroll
        for (int r=0;r<8;r++) acc[r]=0.f;
        for (int kg=0; kg<64; kg++){
            float w0=We1[(4*kg+0)*128+c128], w1=We1[(4*kg+1)*128+c128];
            float w2v=We1[(4*kg+2)*128+c128], w3=We1[(4*kg+3)*128+c128];
#pragma unroll
            for (int r=0;r<8;r++){
                const float4 v = __ldg((const float4*)&sg[(grp*8+r)*SD + 4*kg]);
                acc[r] += v.x*w0 + v.y*w1 + v.z*w2v + v.w*w3;
            }
        }
#pragma unroll
        for (int r=0;r<8;r++) bP[(grp*8+r)*128 + c128] = acc[r];
    }
    float* We1e_s = &sm->hdn[16][0];     // 32 x 128 (hdn rows 16..31)
    for (int idx = tid; idx < 32*128; idx += NT)
        We1e_s[idx] = We1[(256 + (idx>>7))*128 + (idx&127)];
    __syncthreads();

    float* bh = sm->w2s;                 // 16 x 128
    float* ebuf = &sm->esm2[0][0];       // 16 x 32 scratch
    {
        const int c128 = tid & 127;
        const int grp  = tid >> 7;       // 0..3
        const float w288 = We1[288*128 + c128];
        const float bbe  = be1[c128];
        for (int pblk=0; pblk<62; pblk++){
            for (int idx = tid; idx < 16*ED; idx += NT){
                int q = idx>>5, k = idx&31;
                int eL = pblk*16 + q;
                ebuf[q*32+k] = g_e[(ebase+eL)*ED + k];
            }
            if (tid < 16){
                int eL = pblk*16 + tid;
                int i = eL/31, jj = eL - i*31; int j = jj + (jj>=i);
                float rx=sm->pos[j][0]-sm->pos[i][0];
                float ry=sm->pos[j][1]-sm->pos[i][1];
                float rz=sm->pos[j][2]-sm->pos[i][2];
                sm->dbuf[tid] = sqrtf(fmaxf(rx*rx+ry*ry+rz*rz, 1e-6f));
            }
            __syncthreads();
#pragma unroll
            for (int qq=0; qq<4; qq++){
                int q = grp*4 + qq;
                int eL = pblk*16 + q;
                int i = eL/31, jj = eL - i*31; int j = jj + (jj>=i);
                float a = bbe + bP[i*128+c128] + bP[j*128+c128] + sm->dbuf[q]*w288;
#pragma unroll
                for (int kg=0; kg<8; kg++){
                    float4 e4 = ((const float4*)&ebuf[q*32])[kg];
                    a += e4.x*We1e_s[(4*kg+0)*128+c128] + e4.y*We1e_s[(4*kg+1)*128+c128]
                       + e4.z*We1e_s[(4*kg+2)*128+c128] + e4.w*We1e_s[(4*kg+3)*128+c128];
                }
                bh[q*128+c128] = silu_f(a);
            }
            __syncthreads();
            {   // warp wrp handles edge wrp of this chunk
                int qq = wrp;
                int eL = pblk*16 + qq;
#pragma unroll
                for (int b=0;b<5;b++){
                    float part = 0.f;
#pragma unroll
                    for (int m=0;m<4;m++){
                        int cc = lane + 32*m;
                        part += bh[qq*128+cc] * We2[cc*5+b];
                    }
#pragma unroll
                    for (int off=16; off>0; off>>=1)
                        part += __shfl_xor_sync(0xffffffffu, part, off);
                    if (lane==0) outB[(ebase+eL)*5+b] = part + be2[b];
                }
            }
            __syncthreads();
        }
    }
}

extern "C" void kernel_launch(void* const* d_in, const int* in_sizes, int n_in,
                              void* d_out, int out_size)
{
    const float* x    = (const float*)d_in[0];
    const float* z    = (const float*)d_in[1];
    const float* rot  = (const float*)d_in[2];
    // d_in[3] edge_index (int64) unused — structure is static block-dense
    const float* eattr= (const float*)d_in[4];
    // d_in[5] batch (int64) unused
    const float* Wam  = (const float*)d_in[6];
    const float* bam  = (const float*)d_in[7];
    const float* Wbm  = (const float*)d_in[8];
    const float* bbm  = (const float*)d_in[9];
    const float* gW1  = (const float*)d_in[10];
    const float* gb1  = (const float*)d_in[11];
    const float* gW2  = (const float*)d_in[12];
    const float* gb2  = (const float*)d_in[13];
    const float* Wh1  = (const float*)d_in[14];
    const float* bh1  = (const float*)d_in[15];
    const float* Wh2  = (const float*)d_in[16];
    const float* bh2  = (const float*)d_in[17];
    const float* We1  = (const float*)d_in[18];
    const float* be1  = (const float*)d_in[19];
    const float* We2  = (const float*)d_in[20];
    const float* be2  = (const float*)d_in[21];

    float* out  = (float*)d_out;
    float* outA = out;                                   // atoms: N x 16
    float* outB = out + (long)NNODE*16;                  // bonds: E x 5
    float* outP = out + (long)NNODE*16 + (long)ETOT*5;   // pos:   N x 3

    prep_kernel<<<160, 256>>>(gW2);

    const size_t shmem = sizeof(SM);
    cudaFuncSetAttribute(dec_kernel, cudaFuncAttributeMaxDynamicSharedMemorySize, (int)shmem);
    dec_kernel<<<NMOL, NT, shmem>>>(x,z,rot,eattr,Wam,bam,Wbm,bbm,
                                    gW1,gb1,gW2,gb2,Wh1,bh1,Wh2,bh2,
                                    We1,be1,We2,be2,outA,outB,outP);
}

// round 9
// speedup vs baseline: 1.0822x; 1.0671x over previous
#include <cuda_runtime.h>
#include <math.h>

#define NMOL 256
#define NPER 32
#define NNODE 8192
#define EPM 992
#define ETOT (NMOL*EPM)
#define SD 256
#define ED 32
#define MSG_IN 546
#define MSG_OUT 353
#define NT 512
#define HROWS 16

typedef unsigned long long u64;

// global scratch (sanctioned __device__ arrays)
__device__ float g_e[(long)ETOT*ED];                    // edge features (32.5MB, L2)
__device__ __align__(16) float g_w2t[5*64*32*4];        // transposed W2e  [l][c4][k][4]
__device__ __align__(16) float g_Q [(long)NMOL*NPER*SD];
__device__ __align__(16) float g_S0[(long)NMOL*NPER*SD];
__device__ __align__(16) float g_s [(long)NMOL*NPER*SD];

struct SM {
    float P   [NPER][SD];      // 32KB  s @ W1a
    float hdn [NPER][SD];      // 32KB
    float esm2[2][NPER][2*ED]; // 16KB  dup e rows, double-buffered
    float s0q [4][SD];         // 4KB
    float part1[NPER][ED];     // 4KB   c-half-1 partials of [C2]
    float w2p [SD];
    float pos [NPER][3];
    float npos[NPER][3];
    float dbuf[2][NPER];
    float abuf[2][NPER];
    float rnb [2][NPER][3];
    float pdpart[16][3];
};

__device__ __forceinline__ float silu_f(float v){
    return v * (1.0f / (1.0f + __expf(-v)));
}
__device__ __forceinline__ u64 pack2(float x, float y){
    u64 r; asm("mov.b64 %0, {%1, %2};" : "=l"(r) : "f"(x), "f"(y)); return r;
}
__device__ __forceinline__ void unpack2(u64 v, float& x, float& y){
    asm("mov.b64 {%0, %1}, %2;" : "=f"(x), "=f"(y) : "l"(v));
}
__device__ __forceinline__ u64 fma2(u64 a, u64 b, u64 c){
    u64 d; asm("fma.rn.f32x2 %0, %1, %2, %3;" : "=l"(d) : "l"(a), "l"(b), "l"(c)); return d;
}
__device__ __forceinline__ u64 add2(u64 a, u64 b){
    u64 d; asm("add.rn.f32x2 %0, %1, %2;" : "=l"(d) : "l"(a), "l"(b)); return d;
}
__device__ __forceinline__ u64 dup2(float x){ return pack2(x,x); }

// prep: g_w2t[l*8192 + c4*128 + k*4 + cc] = gW2[(l*256+4*c4+cc)*353 + 321 + k]
__global__ void prep_kernel(const float* __restrict__ gW2){
    int idx = blockIdx.x*256 + threadIdx.x;
    if (idx >= 5*8192) return;
    int l = idx >> 13; int rem = idx & 8191;
    int c4 = rem >> 7; int rem2 = rem & 127;
    int k = rem2 >> 2; int cc = rem2 & 3;
    g_w2t[idx] = gW2[((long)l*256 + 4*c4 + cc)*MSG_OUT + 321 + k];
}

__global__ void __launch_bounds__(NT,2) dec_kernel(
    const float* __restrict__ x,   const float* __restrict__ z,
    const float* __restrict__ rot, const float* __restrict__ eattr,
    const float* __restrict__ Wam, const float* __restrict__ bam,
    const float* __restrict__ Wbm, const float* __restrict__ bbm,
    const float* __restrict__ gW1, const float* __restrict__ gb1,
    const float* __restrict__ gW2, const float* __restrict__ gb2,
    const float* __restrict__ Wh1, const float* __restrict__ bh1,
    const float* __restrict__ Wh2, const float* __restrict__ bh2,
    const float* __restrict__ We1, const float* __restrict__ be1,
    const float* __restrict__ We2, const float* __restrict__ be2,
    float* __restrict__ outA, float* __restrict__ outB, float* __restrict__ outP)
{
    extern __shared__ float smraw[];
    SM* sm = (SM*)smraw;
    const int tid  = threadIdx.x;
    const int lane = tid & 31;
    const int wrp  = tid >> 5;        // 0..15
    const int mol  = blockIdx.x;
    const int nodeBase = mol * NPER;
    const long ebase   = (long)mol * EPM;
    const int c  = tid & 255;
    const int hh = tid >> 8;
    const int r0 = hh * HROWS;
    const int p  = tid & 127;         // col-pair (2p,2p+1) for [B]
    const int q4 = tid >> 7;          // row-quarter for [B]
    const int rq = q4 * 8;
    const int g2  = wrp & 7;          // [C2] row group (rows 4g2..4g2+3)
    const int hf  = wrp >> 3;         // [C2] c-half
    float* Qg  = g_Q  + (size_t)mol*NPER*SD;
    float* S0g = g_S0 + (size_t)mol*NPER*SD;
    float* sg  = g_s  + (size_t)mol*NPER*SD;

    // ---------------- Embed ----------------
    {
        float* xz = &sm->hdn[0][0];
        for (int idx = tid; idx < NPER*80; idx += NT){
            int i = idx / 80, k = idx % 80;
            xz[idx] = (k < 16) ? x[(nodeBase+i)*16 + k] : z[(nodeBase+i)*64 + (k-16)];
        }
        __syncthreads();
        float acc[HROWS];
#pragma unroll
        for (int r=0;r<HROWS;r++) acc[r]=0.f;
        for (int kg=0; kg<20; kg++){
            float w0=Wam[(4*kg+0)*259+c], w1=Wam[(4*kg+1)*259+c];
            float w2v=Wam[(4*kg+2)*259+c], w3=Wam[(4*kg+3)*259+c];
#pragma unroll
            for (int r=0;r<HROWS;r++){
                float4 v = ((const float4*)xz)[(r0+r)*20+kg];
                acc[r] += v.x*w0 + v.y*w1 + v.z*w2v + v.w*w3;
            }
        }
        float b = bam[c];
#pragma unroll
        for (int r=0;r<HROWS;r++) sg[(r0+r)*SD + c] = acc[r] + b;
        if (tid < 96){
            int i = tid/3, cc = tid%3;
            float a = bam[256+cc];
            for (int k=0;k<80;k++) a += xz[i*80+k]*Wam[k*259+256+cc];
            sm->npos[i][cc] = a;
        }
        __syncthreads();
        if (tid < 96){
            int i = tid/3, cc = tid%3;
            float pv = 0.f;
#pragma unroll
            for (int q=0;q<3;q++) pv += rot[mol*9 + cc*3 + q]*sm->npos[i][q];
            sm->pos[i][cc] = pv;
        }
    }

    // ---------------- e init ----------------
    for (int idx = tid; idx < EPM*ED; idx += NT){
        int eL = idx >> 5, k = idx & 31;
        const float* ea = &eattr[(ebase+eL)*5];
        float a = bbm[k];
#pragma unroll
        for (int q=0;q<5;q++) a += ea[q]*Wbm[q*ED+k];
        g_e[(ebase+eL)*ED + k] = a;
    }
    __syncthreads();

    // ---------------- 5 layers ----------------
    for (int l=0; l<5; l++){
        const float* W1 = gW1 + (long)l*MSG_IN*SD;
        const float* b1 = gb1 + l*SD;
        const float* W2 = gW2 + (long)l*SD*MSG_OUT;
        const float* b2 = gb2 + l*MSG_OUT;

        if (tid < 256) sm->w2p[tid] = W2[tid*MSG_OUT + 320];
        if (tid < 96) sm->npos[tid/3][tid%3] = 0.f;

        // P = s@W1a -> SMEM
        {
            float acc[HROWS];
#pragma unroll
            for (int r=0;r<HROWS;r++) acc[r]=0.f;
            for (int kg=0; kg<64; kg++){
                float wa0=W1[(4*kg+0)*SD+c], wa1=W1[(4*kg+1)*SD+c];
                float wa2=W1[(4*kg+2)*SD+c], wa3=W1[(4*kg+3)*SD+c];
#pragma unroll
                for (int r=0;r<HROWS;r++){
                    const float4 v = __ldg((const float4*)&sg[(r0+r)*SD + 4*kg]);
                    acc[r] += v.x*wa0 + v.y*wa1 + v.z*wa2 + v.w*wa3;
                }
            }
#pragma unroll
            for (int r=0;r<HROWS;r++) sm->P[r0+r][c]=acc[r];
        }
        // Q = s@W1b + b1 -> global
        {
            float acc[HROWS];
#pragma unroll
            for (int r=0;r<HROWS;r++) acc[r]=0.f;
            for (int kg=0; kg<64; kg++){
                float wb0=W1[(256+4*kg+0)*SD+c], wb1=W1[(256+4*kg+1)*SD+c];
                float wb2=W1[(256+4*kg+2)*SD+c], wb3=W1[(256+4*kg+3)*SD+c];
#pragma unroll
                for (int r=0;r<HROWS;r++){
                    const float4 v = __ldg((const float4*)&sg[(r0+r)*SD + 4*kg]);
                    acc[r] += v.x*wb0 + v.y*wb1 + v.z*wb2 + v.w*wb3;
                }
            }
            float bb = b1[c];
#pragma unroll
            for (int r=0;r<HROWS;r++) Qg[(r0+r)*SD + c] = acc[r]+bb;
        }

        // prologue: stage esm2[0] + geometry for j=0
        for (int idx = tid; idx < NPER*ED; idx += NT){
            int i = idx>>5, k = idx&31;
            float v = 0.f;
            if (i != 0) v = g_e[(ebase + i*31 + 0)*ED + k];
            *(float2*)&sm->esm2[0][i][2*k] = make_float2(v, v);
        }
        if (tid < NPER){
            int i = tid;
            float pix=sm->pos[i][0], piy=sm->pos[i][1], piz=sm->pos[i][2];
            float pjx=sm->pos[0][0], pjy=sm->pos[0][1], pjz=sm->pos[0][2];
            float rx=pjx-pix, ry=pjy-piy, rz=pjz-piz;
            float d = sqrtf(fmaxf(rx*rx+ry*ry+rz*rz, 1e-6f));
            float inv = 1.f/(1.f+d);
            sm->dbuf[0][i]=d; sm->abuf[0][i]=pix*pjx+piy*pjy+piz*pjz;
            if (i==0){rx=0;ry=0;rz=0;}
            sm->rnb[0][i][0]=rx*inv; sm->rnb[0][i][1]=ry*inv; sm->rnb[0][i][2]=rz*inv;
        }
        __syncthreads();

        const u64 w1d2 = __ldg((const u64*)&W1[544*SD + 2*p]);
        const u64 w1e2 = __ldg((const u64*)&W1[545*SD + 2*p]);
        const float b2p = __ldg(&b2[320]);
        const float b2k = __ldg(&b2[321+lane]);
        const float* W1c = W1 + 512*SD;
        const float* wt  = g_w2t + l*8192 + hf*(32*128) + lane*4;

        for (int j=0; j<NPER; j++){
            const int buf = j & 1, nbuf = buf ^ 1;

            // ---- phase 1: [B] hdn = silu(P+Q+e@W1c+d*w1d+a*w1e) ----
            {
                u64 acc[8];
                const u64 Q2 = __ldg((const u64*)&Qg[j*SD + 2*p]);
#pragma unroll
                for (int r=0;r<8;r++){
                    int i = rq + r;
                    u64 t = add2(*(const u64*)&sm->P[i][2*p], Q2);
                    t = fma2(dup2(sm->dbuf[buf][i]), w1d2, t);
                    t = fma2(dup2(sm->abuf[buf][i]), w1e2, t);
                    acc[r] = t;
                }
#pragma unroll 4
                for (int k2=0;k2<16;k2++){
                    u64 w0 = __ldg((const u64*)&W1c[(2*k2  )*SD + 2*p]);
                    u64 w1 = __ldg((const u64*)&W1c[(2*k2+1)*SD + 2*p]);
#pragma unroll
                    for (int r=0;r<8;r++){
                        const ulonglong2 e2 = *(const ulonglong2*)&sm->esm2[buf][rq+r][4*k2];
                        acc[r] = fma2(e2.x, w0, acc[r]);
                        acc[r] = fma2(e2.y, w1, acc[r]);
                    }
                }
                float s0x=0.f, s0y=0.f;
#pragma unroll
                for (int r=0;r<8;r++){
                    int i = rq + r;
                    float hx,hy; unpack2(acc[r],hx,hy);
                    hx = silu_f(hx); hy = silu_f(hy);
                    if (i==j){ hx=0.f; hy=0.f; }
                    *(float2*)&sm->hdn[i][2*p] = make_float2(hx,hy);
                    s0x += hx; s0y += hy;
                }
                *(float2*)&sm->s0q[q4][2*p] = make_float2(s0x,s0y);
            }
            __syncthreads();

            // ---- phase 2: [C0] S0, [C1] pos scalars, [C2] partial e-updates ----
            float pr[4];
            {
                if (tid < 256)
                    S0g[j*SD + tid] = sm->s0q[0][tid] + sm->s0q[1][tid]
                                    + sm->s0q[2][tid] + sm->s0q[3][tid];
                // [C1]
                {
                    float pdx=0.f, pdy=0.f, pdz=0.f;
#pragma unroll
                    for (int r=0;r<2;r++){
                        int i = wrp + 16*r;
                        float part = 0.f;
#pragma unroll
                        for (int m=0;m<8;m++)
                            part += sm->hdn[i][lane+32*m] * sm->w2p[lane+32*m];
#pragma unroll
                        for (int off=16; off>0; off>>=1)
                            part += __shfl_xor_sync(0xffffffffu, part, off);
                        if (lane==0){
                            float t = part + b2p;
                            pdx += sm->rnb[buf][i][0]*t;
                            pdy += sm->rnb[buf][i][1]*t;
                            pdz += sm->rnb[buf][i][2]*t;
                        }
                    }
                    if (lane==0){ sm->pdpart[wrp][0]=pdx; sm->pdpart[wrp][1]=pdy; sm->pdpart[wrp][2]=pdz; }
                }
                // [C2] partials: rows 4g2..4g2+3, c-half hf, k=lane
                {
                    const int cbase = hf*128;
                    u64 a[4] = {0ULL,0ULL,0ULL,0ULL};
#pragma unroll 8
                    for (int c4=0;c4<32;c4++){
                        ulonglong2 ww = *(const ulonglong2*)&wt[c4*128];
#pragma unroll
                        for (int r=0;r<4;r++){
                            ulonglong2 hv = *(const ulonglong2*)&sm->hdn[4*g2+r][cbase + 4*c4];
                            a[r]=fma2(hv.x,ww.x,a[r]); a[r]=fma2(hv.y,ww.y,a[r]);
                        }
                    }
#pragma unroll
                    for (int r=0;r<4;r++){
                        float ax,ay; unpack2(a[r],ax,ay);
                        pr[r] = ax+ay;
                    }
                    if (hf == 1){
#pragma unroll
                        for (int r=0;r<4;r++) sm->part1[4*g2+r][lane] = pr[r];
                    }
                }
            }
            __syncthreads();

            // ---- phase 3: combine + g_e write (hf=0 warps) | fold/restage (hf=1) ----
            if (hf == 0){
#pragma unroll
                for (int r=0;r<4;r++){
                    int i = 4*g2 + r;
                    if (i != j){
                        int eL = i*31 + j - (j>i);
                        g_e[(ebase+eL)*ED + lane] =
                            pr[r] + sm->part1[i][lane] + b2k + sm->esm2[buf][i][2*lane];
                    }
                }
            } else {
                int t2 = tid - 256;
                if (t2 < 3){
                    float sum=0.f;
#pragma unroll
                    for (int w=0;w<16;w++) sum += sm->pdpart[w][t2];
                    sm->npos[j][t2] += sum;
                }
                if (j < 31){
#pragma unroll
                    for (int it=0; it<4; it++){
                        int idx = t2 + 256*it;
                        int i = idx>>5, k = idx&31;
                        float v = 0.f;
                        if (i != j+1) v = g_e[(ebase + i*31 + (j+1) - ((j+1)>i))*ED + k];
                        *(float2*)&sm->esm2[nbuf][i][2*k] = make_float2(v, v);
                    }
                    if (t2 >= 64 && t2 < 96){
                        int i = t2 - 64;
                        float pix=sm->pos[i][0], piy=sm->pos[i][1], piz=sm->pos[i][2];
                        float pjx=sm->pos[j+1][0], pjy=sm->pos[j+1][1], pjz=sm->pos[j+1][2];
                        float rx=pjx-pix, ry=pjy-piy, rz=pjz-piz;
                        float d = sqrtf(fmaxf(rx*rx+ry*ry+rz*rz, 1e-6f));
                        float inv = 1.f/(1.f+d);
                        sm->dbuf[nbuf][i]=d; sm->abuf[nbuf][i]=pix*pjx+piy*pjy+piz*pjz;
                        if (i==j+1){rx=0;ry=0;rz=0;}
                        sm->rnb[nbuf][i][0]=rx*inv; sm->rnb[nbuf][i][1]=ry*inv; sm->rnb[nbuf][i][2]=rz*inv;
                    }
                }
            }
            __syncthreads();
        } // j

        // s += (S0 @ W2s)/31 + b2s
        {
            float acc[HROWS];
#pragma unroll
            for (int r=0;r<HROWS;r++) acc[r]=0.f;
            for (int kg=0; kg<64; kg++){
                float w0=W2[(4*kg+0)*MSG_OUT+c], w1=W2[(4*kg+1)*MSG_OUT+c];
                float w2v=W2[(4*kg+2)*MSG_OUT+c], w3=W2[(4*kg+3)*MSG_OUT+c];
#pragma unroll
                for (int r=0;r<HROWS;r++){
                    const float4 v = __ldg((const float4*)&S0g[(r0+r)*SD + 4*kg]);
                    acc[r] += v.x*w0 + v.y*w1 + v.z*w2v + v.w*w3;
                }
            }
            float b2s = b2[c];
#pragma unroll
            for (int r=0;r<HROWS;r++)
                sg[(r0+r)*SD + c] += acc[r]*(1.f/31.f) + b2s;
        }
        if (tid<96){
            int i = tid/3, cc = tid%3;
            sm->pos[i][cc] += sm->npos[i][cc]*(1.f/31.f);
        }
        __syncthreads();
    } // layers

    // ---------------- atoms + pos out ----------------
    {
        float acc[HROWS];
#pragma unroll
        for (int r=0;r<HROWS;r++) acc[r]=0.f;
        for (int kg=0; kg<64; kg++){
            float w0=Wh1[(4*kg+0)*SD+c], w1=Wh1[(4*kg+1)*SD+c];
            float w2v=Wh1[(4*kg+2)*SD+c], w3=Wh1[(4*kg+3)*SD+c];
#pragma unroll
            for (int r=0;r<HROWS;r++){
                const float4 v = __ldg((const float4*)&sg[(r0+r)*SD + 4*kg]);
                acc[r] += v.x*w0 + v.y*w1 + v.z*w2v + v.w*w3;
            }
        }
        float bb = bh1[c];
#pragma unroll
        for (int r=0;r<HROWS;r++) sm->P[r0+r][c] = silu_f(acc[r]+bb);
    }
    __syncthreads();
    for (int o = tid; o < NPER*16; o += NT){
        int i = o>>4, cc = o&15;
        float a = bh2[cc];
        for (int k=0;k<SD;k++) a += sm->P[i][k]*Wh2[k*16+cc];
        outA[(nodeBase+i)*16+cc] = a;
    }
    if (tid < 96){
        int i = tid/3, cc = tid%3;
        outP[(nodeBase+i)*3+cc] = sm->pos[i][cc];
    }
    __syncthreads();

    // ---------------- bonds ----------------
    float* bP = &sm->hdn[0][0];          // 32 x 128
    {
        const int c128 = tid & 127;
        const int grp  = tid >> 7;
        float acc[8];
#pragma unroll
        for (int r=0;r<8;r++) acc[r]=0.f;
        for (int kg=0; kg<64; kg++){
            float w0=We1[(4*kg+0)*128+c128], w1=We1[(4*kg+1)*128+c128];
            float w2v=We1[(4*kg+2)*128+c128], w3=We1[(4*kg+3)*128+c128];
#pragma unroll
            for (int r=0;r<8;r++){
                const float4 v = __ldg((const float4*)&sg[(grp*8+r)*SD + 4*kg]);
                acc[r] += v.x*w0 + v.y*w1 + v.z*w2v + v.w*w3;
            }
        }
#pragma unroll
        for (int r=0;r<8;r++) bP[(grp*8+r)*128 + c128] = acc[r];
    }
    float* We1e_s = &sm->hdn[16][0];     // 32 x 128
    for (int idx = tid; idx < 32*128; idx += NT)
        We1e_s[idx] = We1[(256 + (idx>>7))*128 + (idx&127)];
    __syncthreads();

    float* bh = &sm->P[0][0];            // 16 x 128 scratch
    float* ebuf = &sm->esm2[0][0][0];    // 16 x 32 scratch
    {
        const int c128 = tid & 127;
        const int grp  = tid >> 7;
        const float w288 = We1[288*128 + c128];
        const float bbe  = be1[c128];
        for (int pblk=0; pblk<62; pblk++){
            for (int idx = tid; idx < 16*ED; idx += NT){
                int q = idx>>5, k = idx&31;
                int eL = pblk*16 + q;
                ebuf[q*32+k] = g_e[(ebase+eL)*ED + k];
            }
            if (tid < 16){
                int eL = pblk*16 + tid;
                int i = eL/31, jj = eL - i*31; int j = jj + (jj>=i);
                float rx=sm->pos[j][0]-sm->pos[i][0];
                float ry=sm->pos[j][1]-sm->pos[i][1];
                float rz=sm->pos[j][2]-sm->pos[i][2];
                sm->dbuf[0][tid] = sqrtf(fmaxf(rx*rx+ry*ry+rz*rz, 1e-6f));
            }
            __syncthreads();
#pragma unroll
            for (int qq=0; qq<4; qq++){
                int q = grp*4 + qq;
                int eL = pblk*16 + q;
                int i = eL/31, jj = eL - i*31; int j = jj + (jj>=i);
                float a = bbe + bP[i*128+c128] + bP[j*128+c128] + sm->dbuf[0][q]*w288;
#pragma unroll
                for (int kg=0; kg<8; kg++){
                    float4 e4 = ((const float4*)&ebuf[q*32])[kg];
                    a += e4.x*We1e_s[(4*kg+0)*128+c128] + e4.y*We1e_s[(4*kg+1)*128+c128]
                       + e4.z*We1e_s[(4*kg+2)*128+c128] + e4.w*We1e_s[(4*kg+3)*128+c128];
                }
                bh[q*128+c128] = silu_f(a);
            }
            __syncthreads();
            {
                int qq = wrp;
                int eL = pblk*16 + qq;
#pragma unroll
                for (int b=0;b<5;b++){
                    float part = 0.f;
#pragma unroll
                    for (int m=0;m<4;m++){
                        int cc = lane + 32*m;
                        part += bh[qq*128+cc] * We2[cc*5+b];
                    }
#pragma unroll
                    for (int off=16; off>0; off>>=1)
                        part += __shfl_xor_sync(0xffffffffu, part, off);
                    if (lane==0) outB[(ebase+eL)*5+b] = part + be2[b];
                }
            }
            __syncthreads();
        }
    }
}

extern "C" void kernel_launch(void* const* d_in, const int* in_sizes, int n_in,
                              void* d_out, int out_size)
{
    const float* x    = (const float*)d_in[0];
    const float* z    = (const float*)d_in[1];
    const float* rot  = (const float*)d_in[2];
    const float* eattr= (const float*)d_in[4];
    const float* Wam  = (const float*)d_in[6];
    const float* bam  = (const float*)d_in[7];
    const float* Wbm  = (const float*)d_in[8];
    const float* bbm  = (const float*)d_in[9];
    const float* gW1  = (const float*)d_in[10];
    const float* gb1  = (const float*)d_in[11];
    const float* gW2  = (const float*)d_in[12];
    const float* gb2  = (const float*)d_in[13];
    const float* Wh1  = (const float*)d_in[14];
    const float* bh1  = (const float*)d_in[15];
    const float* Wh2  = (const float*)d_in[16];
    const float* bh2  = (const float*)d_in[17];
    const float* We1  = (const float*)d_in[18];
    const float* be1  = (const float*)d_in[19];
    const float* We2  = (const float*)d_in[20];
    const float* be2  = (const float*)d_in[21];

    float* out  = (float*)d_out;
    float* outA = out;
    float* outB = out + (long)NNODE*16;
    float* outP = out + (long)NNODE*16 + (long)ETOT*5;

    prep_kernel<<<160, 256>>>(gW2);

    const size_t shmem = sizeof(SM);
    cudaFuncSetAttribute(dec_kernel, cudaFuncAttributeMaxDynamicSharedMemorySize, (int)shmem);
    dec_kernel<<<NMOL, NT, shmem>>>(x,z,rot,eattr,Wam,bam,Wbm,bbm,
                                    gW1,gb1,gW2,gb2,Wh1,bh1,Wh2,bh2,
                                    We1,be1,We2,be2,outA,outB,outP);
}